// round 14
// baseline (speedup 1.0000x reference)
#include <cuda_runtime.h>

#define NN 50000
#define EE 800000
#define DH 64
#define APS 68    // f32 A-tile row stride (conflict-free 32-bit frag loads)
#define ARS 136   // (hi,lo)-pair W-tile row stride (half-K buffer: 32 rows)

// ---- scratch (device globals; no allocation allowed) ----
__device__ float g_h[NN * DH];
__device__ float g_P[NN * DH];
__device__ float g_Q[NN * DH];
__device__ float g_aggH[NN * DH];
__device__ float g_W2U[3 * DH * DH];   // W2 @ U1b per layer
__device__ float g_b2U[3 * DH];        // b2 @ U1b per layer
__device__ float g_CWP[3 * DH];        // in_w @ W1a[0]
__device__ float g_CWQ[3 * DH];        // in_w @ W1b[0]
__device__ float g_cbP[DH];
__device__ float g_cbQ[DH];
__device__ int   g_hist[NN];
__device__ int   g_bsum[256];
__device__ int   g_off[NN + 1];
__device__ int   g_cur[NN];
__device__ int   g_rows[EE];

// ---- tf32 helpers ----
__device__ __forceinline__ void dec2(float a, float& hi, float& lo) {
    unsigned int hb;
    asm("cvt.rna.tf32.f32 %0, %1;" : "=r"(hb) : "f"(a));
    hi = __uint_as_float(hb);
    float r = a - hi;
    unsigned int lb;
    asm("cvt.rna.tf32.f32 %0, %1;" : "=r"(lb) : "f"(r));
    lo = __uint_as_float(lb);
}

#define MMA(c0, c1, c2, c3, a0, a1, a2, a3, b0, b1)                          \
    asm volatile("mma.sync.aligned.m16n8k8.row.col.f32.tf32.tf32.f32 "       \
                 "{%0,%1,%2,%3}, {%4,%5,%6,%7}, {%8,%9}, {%0,%1,%2,%3};"     \
                 : "+f"(c0), "+f"(c1), "+f"(c2), "+f"(c3)                    \
                 : "r"(a0), "r"(a1), "r"(a2), "r"(a3), "r"(b0), "r"(b1))

// stage 128x64 activation tile as PLAIN f32, row stride APS
#define STAGE_A(SRC)                                                         \
    _Pragma("unroll")                                                        \
    for (int it_ = 0; it_ < 8; it_++) {                                      \
        int q_ = it_ * 256 + t;                                              \
        int i_ = q_ >> 4, j4_ = (q_ & 15) * 4;                               \
        float4 v_ = make_float4(0.f, 0.f, 0.f, 0.f);                         \
        if (base + i_ < n) v_ = *(const float4*)&(SRC)[(base + i_) * DH + j4_]; \
        *(float4*)&As[i_ * APS + j4_] = v_;                                  \
    }

// stage 32x64 HALF of a weight tile (k rows [KB, KB+32)), decomposed pairs
#define STAGE_WH(SRC, KB)                                                    \
    _Pragma("unroll")                                                        \
    for (int it_ = 0; it_ < 2; it_++) {                                      \
        int q_ = it_ * 256 + t;                                              \
        int k_ = q_ >> 4, j4_ = (q_ & 15) * 4;                               \
        float4 v_ = *(const float4*)&(SRC)[((KB) + k_) * DH + j4_];          \
        float h0_, l0_, h1_, l1_;                                            \
        dec2(v_.x, h0_, l0_); dec2(v_.y, h1_, l1_);                          \
        *(float4*)&WHL[k_ * ARS + 2 * j4_] = make_float4(h0_, l0_, h1_, l1_); \
        dec2(v_.z, h0_, l0_); dec2(v_.w, h1_, l1_);                          \
        *(float4*)&WHL[k_ * ARS + 2 * j4_ + 4] = make_float4(h0_, l0_, h1_, l1_); \
    }

// half-K (32) GEMM chunk via 3xTF32 mma; A (f32) decomposed on the fly.
#define MMA_HALF(ACC, KB)                                                    \
    _Pragma("unroll 2")                                                      \
    for (int k0_ = 0; k0_ < 32; k0_ += 8) {                                  \
        float a00_ = As[(row0 + gq) * APS + (KB) + k0_ + t4];                \
        float a10_ = As[(row0 + gq + 8) * APS + (KB) + k0_ + t4];            \
        float a01_ = As[(row0 + gq) * APS + (KB) + k0_ + t4 + 4];            \
        float a11_ = As[(row0 + gq + 8) * APS + (KB) + k0_ + t4 + 4];        \
        float h_, l_;                                                        \
        dec2(a00_, h_, l_);                                                  \
        unsigned ah0 = __float_as_uint(h_), al0 = __float_as_uint(l_);       \
        dec2(a10_, h_, l_);                                                  \
        unsigned ah1 = __float_as_uint(h_), al1 = __float_as_uint(l_);       \
        dec2(a01_, h_, l_);                                                  \
        unsigned ah2 = __float_as_uint(h_), al2 = __float_as_uint(l_);       \
        dec2(a11_, h_, l_);                                                  \
        unsigned ah3 = __float_as_uint(h_), al3 = __float_as_uint(l_);       \
        _Pragma("unroll")                                                    \
        for (int nt_ = 0; nt_ < 8; nt_++) {                                  \
            float2 fb0 = *(const float2*)&WHL[(k0_ + t4) * ARS + 2 * (nt_ * 8 + gq)];     \
            float2 fb1 = *(const float2*)&WHL[(k0_ + t4 + 4) * ARS + 2 * (nt_ * 8 + gq)]; \
            unsigned bh0 = __float_as_uint(fb0.x), bl0 = __float_as_uint(fb0.y); \
            unsigned bh1 = __float_as_uint(fb1.x), bl1 = __float_as_uint(fb1.y); \
            MMA(ACC[nt_][0], ACC[nt_][1], ACC[nt_][2], ACC[nt_][3],          \
                ah0, ah1, ah2, ah3, bh0, bh1);                               \
            MMA(ACC[nt_][0], ACC[nt_][1], ACC[nt_][2], ACC[nt_][3],          \
                ah0, ah1, ah2, ah3, bl0, bl1);                               \
            MMA(ACC[nt_][0], ACC[nt_][1], ACC[nt_][2], ACC[nt_][3],          \
                al0, al1, al2, al3, bh0, bh1);                               \
        }                                                                    \
    }

// full 64-K pass = two half-K chunks with W restaged between
#define MMA_PASS2(ACC, WSRC)                                                 \
    STAGE_WH(WSRC, 0)                                                        \
    __syncthreads();                                                         \
    MMA_HALF(ACC, 0)                                                         \
    __syncthreads();                                                         \
    STAGE_WH(WSRC, 32)                                                       \
    __syncthreads();                                                         \
    MMA_HALF(ACC, 32)

// classic f32 macro (k_out only)
#define GEMM_8x4(AS, I0, WS_PTR, WSTRIDE, ACC)                                  \
    _Pragma("unroll 4")                                                          \
    for (int k0 = 0; k0 < 64; k0 += 4) {                                         \
        float4 w0 = *(const float4*)&(WS_PTR)[(k0 + 0) * (WSTRIDE) + j0];        \
        float4 w1 = *(const float4*)&(WS_PTR)[(k0 + 1) * (WSTRIDE) + j0];        \
        float4 w2 = *(const float4*)&(WS_PTR)[(k0 + 2) * (WSTRIDE) + j0];        \
        float4 w3 = *(const float4*)&(WS_PTR)[(k0 + 3) * (WSTRIDE) + j0];        \
        _Pragma("unroll")                                                        \
        for (int r = 0; r < 8; r++) {                                            \
            float4 a4 = *(const float4*)&(AS)[((I0) + r) * DH + k0];             \
            ACC[r][0] = fmaf(a4.x, w0.x, ACC[r][0]);                             \
            ACC[r][1] = fmaf(a4.x, w0.y, ACC[r][1]);                             \
            ACC[r][2] = fmaf(a4.x, w0.z, ACC[r][2]);                             \
            ACC[r][3] = fmaf(a4.x, w0.w, ACC[r][3]);                             \
            ACC[r][0] = fmaf(a4.y, w1.x, ACC[r][0]);                             \
            ACC[r][1] = fmaf(a4.y, w1.y, ACC[r][1]);                             \
            ACC[r][2] = fmaf(a4.y, w1.z, ACC[r][2]);                             \
            ACC[r][3] = fmaf(a4.y, w1.w, ACC[r][3]);                             \
            ACC[r][0] = fmaf(a4.z, w2.x, ACC[r][0]);                             \
            ACC[r][1] = fmaf(a4.z, w2.y, ACC[r][1]);                             \
            ACC[r][2] = fmaf(a4.z, w2.z, ACC[r][2]);                             \
            ACC[r][3] = fmaf(a4.z, w2.w, ACC[r][3]);                             \
            ACC[r][0] = fmaf(a4.w, w3.x, ACC[r][0]);                             \
            ACC[r][1] = fmaf(a4.w, w3.y, ACC[r][1]);                             \
            ACC[r][2] = fmaf(a4.w, w3.z, ACC[r][2]);                             \
            ACC[r][3] = fmaf(a4.w, w3.w, ACC[r][3]);                             \
        }                                                                        \
    }

// =====================================================================
// Fused input: h = x@in_w + in_b ; P0 = x@CWP + cbP ; Q0 = x@CWQ + cbQ
// =====================================================================
__global__ void k_input(const float* __restrict__ x, const float* __restrict__ w,
                        const float* __restrict__ b, int n) {
    int t = blockIdx.x * blockDim.x + threadIdx.x;
    if (t >= n * DH) return;
    int i = t / DH, j = t % DH;
    float x0 = x[i * 3 + 0], x1 = x[i * 3 + 1], x2 = x[i * 3 + 2];
    g_h[t] = fmaf(x0, w[0 * DH + j], fmaf(x1, w[1 * DH + j],
             fmaf(x2, w[2 * DH + j], b[j])));
    g_P[t] = fmaf(x0, g_CWP[0 * DH + j], fmaf(x1, g_CWP[1 * DH + j],
             fmaf(x2, g_CWP[2 * DH + j], g_cbP[j])));
    g_Q[t] = fmaf(x0, g_CWQ[0 * DH + j], fmaf(x1, g_CWQ[1 * DH + j],
             fmaf(x2, g_CWQ[2 * DH + j], g_cbQ[j])));
}

// =====================================================================
// Counting sort of edges by destination (built once, used 3 layers)
// hist/scatter batched 4 edges/thread (MLP 4)
// =====================================================================
__global__ void k_zero_hist(int n) {
    int t = blockIdx.x * blockDim.x + threadIdx.x;
    if (t < n) g_hist[t] = 0;
}
__global__ void k_hist(const int* __restrict__ col, int e) {
    int b = (blockIdx.x * blockDim.x + threadIdx.x) * 4;
    if (b + 3 < e) {
        int4 c = *(const int4*)&col[b];
        atomicAdd(&g_hist[c.x], 1);
        atomicAdd(&g_hist[c.y], 1);
        atomicAdd(&g_hist[c.z], 1);
        atomicAdd(&g_hist[c.w], 1);
    } else {
        for (int i = b; i < e; i++) atomicAdd(&g_hist[col[i]], 1);
    }
}
__global__ void k_blocksum(int n) {
    __shared__ int ss[256];
    int t = threadIdx.x, i = blockIdx.x * 256 + t;
    ss[t] = (i < n) ? g_hist[i] : 0;
    __syncthreads();
    for (int o = 128; o > 0; o >>= 1) {
        if (t < o) ss[t] += ss[t + o];
        __syncthreads();
    }
    if (t == 0) g_bsum[blockIdx.x] = ss[0];
}
__global__ void k_offsets(int n, int e) {
    __shared__ int ss[256];
    int t = threadIdx.x, i = blockIdx.x * 256 + t;
    ss[t] = (t < blockIdx.x) ? g_bsum[t] : 0;
    __syncthreads();
    for (int o = 128; o > 0; o >>= 1) {
        if (t < o) ss[t] += ss[t + o];
        __syncthreads();
    }
    int bpre = ss[0];
    __syncthreads();
    int h = (i < n) ? g_hist[i] : 0;
    ss[t] = h;
    __syncthreads();
    for (int o = 1; o < 256; o <<= 1) {
        int v = (t >= o) ? ss[t - o] : 0;
        __syncthreads();
        ss[t] += v;
        __syncthreads();
    }
    int excl = ss[t] - h + bpre;
    if (i < n) {
        g_off[i] = excl; g_cur[i] = excl;
        if (i == n - 1) g_off[n] = e;
    }
}
__global__ void k_scatter(const int* __restrict__ row, const int* __restrict__ col,
                          int e) {
    int b = (blockIdx.x * blockDim.x + threadIdx.x) * 4;
    if (b + 3 < e) {
        int4 c = *(const int4*)&col[b];
        int4 r = *(const int4*)&row[b];
        int p0 = atomicAdd(&g_cur[c.x], 1);
        int p1 = atomicAdd(&g_cur[c.y], 1);
        int p2 = atomicAdd(&g_cur[c.z], 1);
        int p3 = atomicAdd(&g_cur[c.w], 1);
        g_rows[p0] = r.x; g_rows[p1] = r.y;
        g_rows[p2] = r.z; g_rows[p3] = r.w;
    } else {
        for (int i = b; i < e; i++) {
            int pos = atomicAdd(&g_cur[col[i]], 1);
            g_rows[pos] = row[i];
        }
    }
}

// =====================================================================
// Precompute: blocks 0..2 -> W2U[l], b2U[l]; block 3 -> input composites
// =====================================================================
__global__ void k_prep_all(const float* __restrict__ msg_w2,
                           const float* __restrict__ upd_w1,
                           const float* __restrict__ msg_b2,
                           const float* __restrict__ msg_w1,
                           const float* __restrict__ in_w,
                           const float* __restrict__ in_b) {
    int t = threadIdx.x;
    if (blockIdx.x < 3) {
        int l = blockIdx.x;
        const float* w2  = msg_w2 + l * DH * DH;
        const float* u1b = upd_w1 + l * 2 * DH * DH + DH * DH;
        const float* b2  = msg_b2 + l * DH;
        __shared__ __align__(16) float W2s[DH * DH];
        __shared__ __align__(16) float U1s[DH * DH];
        __shared__ float b2s[DH];
        for (int q = t; q < DH * DH / 4; q += 256) {
            *(float4*)&W2s[q * 4] = *(const float4*)&w2[q * 4];
            *(float4*)&U1s[q * 4] = *(const float4*)&u1b[q * 4];
        }
        if (t < DH) b2s[t] = b2[t];
        __syncthreads();
        for (int idx = t; idx < DH * DH; idx += 256) {
            int k = idx >> 6, j = idx & 63;
            float s = 0.f;
            #pragma unroll 8
            for (int m = 0; m < DH; m++) s = fmaf(W2s[k * DH + m], U1s[m * DH + j], s);
            g_W2U[l * DH * DH + idx] = s;
        }
        if (t < DH) {
            float s = 0.f;
            #pragma unroll 8
            for (int m = 0; m < DH; m++) s = fmaf(b2s[m], U1s[m * DH + t], s);
            g_b2U[l * DH + t] = s;
        }
    } else {
        __shared__ __align__(16) float W1s[2 * DH * DH];
        __shared__ float iws[3 * DH];
        __shared__ float ibs[DH];
        for (int q = t; q < 2 * DH * DH / 4; q += 256)
            *(float4*)&W1s[q * 4] = *(const float4*)&msg_w1[q * 4];
        if (t < 3 * DH) iws[t] = in_w[t];
        if (t < DH) ibs[t] = in_b[t];
        __syncthreads();
        for (int idx = t; idx < 3 * DH; idx += 256) {
            int r = idx >> 6, j = idx & 63;
            float sp = 0.f, sq = 0.f;
            #pragma unroll 8
            for (int k = 0; k < DH; k++) {
                float iv = iws[r * DH + k];
                sp = fmaf(iv, W1s[k * DH + j], sp);
                sq = fmaf(iv, W1s[(DH + k) * DH + j], sq);
            }
            g_CWP[idx] = sp; g_CWQ[idx] = sq;
        }
        if (t < DH) {
            float sp = 0.f, sq = 0.f;
            #pragma unroll 8
            for (int k = 0; k < DH; k++) {
                sp = fmaf(ibs[k], W1s[k * DH + t], sp);
                sq = fmaf(ibs[k], W1s[(DH + k) * DH + t], sq);
            }
            g_cbP[t] = sp; g_cbQ[t] = sq;
        }
    }
}

// =====================================================================
// CSR aggregation: aggH[v] = sum_{e: dst=v} relu(P[src_e] + Q[v] + b1)
// =====================================================================
__global__ void __launch_bounds__(256)
k_agg(const float* __restrict__ b1, int n) {
    int node = blockIdx.x * 16 + (threadIdx.x >> 4);
    int l4 = (threadIdx.x & 15) * 4;
    if (node >= n) return;
    int s = g_off[node], en = g_off[node + 1];
    float4 q = *(const float4*)&g_Q[node * DH + l4];
    float4 b = *(const float4*)&b1[l4];
    q.x += b.x; q.y += b.y; q.z += b.z; q.w += b.w;
    float4 acc = make_float4(0.f, 0.f, 0.f, 0.f);
    int e = s;
    for (; e + 4 <= en; e += 4) {
        int r0 = __ldg(&g_rows[e + 0]);
        int r1 = __ldg(&g_rows[e + 1]);
        int r2 = __ldg(&g_rows[e + 2]);
        int r3 = __ldg(&g_rows[e + 3]);
        float4 p0 = *(const float4*)&g_P[r0 * DH + l4];
        float4 p1 = *(const float4*)&g_P[r1 * DH + l4];
        float4 p2 = *(const float4*)&g_P[r2 * DH + l4];
        float4 p3 = *(const float4*)&g_P[r3 * DH + l4];
        acc.x += fmaxf(p0.x + q.x, 0.f) + fmaxf(p1.x + q.x, 0.f)
               + fmaxf(p2.x + q.x, 0.f) + fmaxf(p3.x + q.x, 0.f);
        acc.y += fmaxf(p0.y + q.y, 0.f) + fmaxf(p1.y + q.y, 0.f)
               + fmaxf(p2.y + q.y, 0.f) + fmaxf(p3.y + q.y, 0.f);
        acc.z += fmaxf(p0.z + q.z, 0.f) + fmaxf(p1.z + q.z, 0.f)
               + fmaxf(p2.z + q.z, 0.f) + fmaxf(p3.z + q.z, 0.f);
        acc.w += fmaxf(p0.w + q.w, 0.f) + fmaxf(p1.w + q.w, 0.f)
               + fmaxf(p2.w + q.w, 0.f) + fmaxf(p3.w + q.w, 0.f);
    }
    for (; e < en; e++) {
        int rr = __ldg(&g_rows[e]);
        float4 p = *(const float4*)&g_P[rr * DH + l4];
        acc.x += fmaxf(p.x + q.x, 0.f);
        acc.y += fmaxf(p.y + q.y, 0.f);
        acc.z += fmaxf(p.z + q.z, 0.f);
        acc.w += fmaxf(p.w + q.w, 0.f);
    }
    *(float4*)&g_aggH[node * DH + l4] = acc;
}

// =====================================================================
// Node update via 3xTF32 mma (A f32; W staged in two k-halves)
// + next-layer P/Q epilogue.  smem ~53KB -> occ 4.
// =====================================================================
__global__ void __launch_bounds__(256, 4)
k_update(const float* __restrict__ u1a, const float* __restrict__ ub1,
         const float* __restrict__ u2, const float* __restrict__ ub2,
         int l, int n, const float* __restrict__ w1_next) {
    extern __shared__ float sm[];
    float* As   = sm;                 // [128][APS] plain f32
    float* WHL  = sm + 128 * APS;     // [32][ARS]  half-K (hi,lo) pairs
    float* ub1s = WHL + 32 * ARS;
    float* ub2s = ub1s + 64;
    float* b2Us = ub2s + 64;
    int t = threadIdx.x;
    int w = t >> 5, lane = t & 31;
    int gq = lane >> 2, t4 = lane & 3;
    int base = blockIdx.x * 128;
    int row0 = w * 16;

    if (t < 64) { ub1s[t] = ub1[t]; ub2s[t] = ub2[t]; b2Us[t] = g_b2U[l * DH + t]; }

    float C[8][4];
    #pragma unroll
    for (int nt = 0; nt < 8; nt++)
        C[nt][0] = C[nt][1] = C[nt][2] = C[nt][3] = 0.f;

    // passes 0,1: h@U1a + aggH@W2U (accumulated together)
    for (int pass = 0; pass < 2; pass++) {
        __syncthreads();
        const float* a_src = pass ? g_aggH : g_h;
        const float* wsrc  = pass ? (g_W2U + l * DH * DH) : u1a;
        STAGE_A(a_src)
        MMA_PASS2(C, wsrc)
    }
    __syncthreads();

    // epilogue 1: hid = relu(pre + deg*b2U + ub1) -> As (f32)
    {
        int i0g = base + row0 + gq, i1g = i0g + 8;
        float dg0 = (i0g < n) ? (float)(g_off[i0g + 1] - g_off[i0g]) : 0.f;
        float dg1 = (i1g < n) ? (float)(g_off[i1g + 1] - g_off[i1g]) : 0.f;
        #pragma unroll
        for (int nt = 0; nt < 8; nt++) {
            int j0c = nt * 8 + 2 * t4, j1c = j0c + 1;
            float v00 = fmaxf(C[nt][0] + dg0 * b2Us[j0c] + ub1s[j0c], 0.f);
            float v01 = fmaxf(C[nt][1] + dg0 * b2Us[j1c] + ub1s[j1c], 0.f);
            float v10 = fmaxf(C[nt][2] + dg1 * b2Us[j0c] + ub1s[j0c], 0.f);
            float v11 = fmaxf(C[nt][3] + dg1 * b2Us[j1c] + ub1s[j1c], 0.f);
            *(float2*)&As[(row0 + gq) * APS + j0c] = make_float2(v00, v01);
            *(float2*)&As[(row0 + gq + 8) * APS + j0c] = make_float2(v10, v11);
        }
    }
    // need As writes visible to all warps before MMA reads them
    __syncthreads();

    #pragma unroll
    for (int nt = 0; nt < 8; nt++)
        C[nt][0] = C[nt][1] = C[nt][2] = C[nt][3] = 0.f;
    MMA_PASS2(C, u2)
    __syncthreads();

    // epilogue 2: h = relu(C + ub2) -> gmem (+ As if P/Q needed)
    {
        int i0g = base + row0 + gq, i1g = i0g + 8;
        #pragma unroll
        for (int nt = 0; nt < 8; nt++) {
            int j0c = nt * 8 + 2 * t4, j1c = j0c + 1;
            float v00 = fmaxf(C[nt][0] + ub2s[j0c], 0.f);
            float v01 = fmaxf(C[nt][1] + ub2s[j1c], 0.f);
            float v10 = fmaxf(C[nt][2] + ub2s[j0c], 0.f);
            float v11 = fmaxf(C[nt][3] + ub2s[j1c], 0.f);
            if (i0g < n) *(float2*)&g_h[i0g * DH + j0c] = make_float2(v00, v01);
            if (i1g < n) *(float2*)&g_h[i1g * DH + j0c] = make_float2(v10, v11);
            if (w1_next) {
                *(float2*)&As[(row0 + gq) * APS + j0c] = make_float2(v00, v01);
                *(float2*)&As[(row0 + gq + 8) * APS + j0c] = make_float2(v10, v11);
            }
        }
    }

    if (w1_next) {
        for (int pass = 0; pass < 2; pass++) {
            __syncthreads();
            #pragma unroll
            for (int nt = 0; nt < 8; nt++)
                C[nt][0] = C[nt][1] = C[nt][2] = C[nt][3] = 0.f;
            MMA_PASS2(C, w1_next + pass * 64 * DH)
            float* dst = pass ? g_Q : g_P;
            int i0g = base + row0 + gq, i1g = i0g + 8;
            #pragma unroll
            for (int nt = 0; nt < 8; nt++) {
                int j0c = nt * 8 + 2 * t4;
                if (i0g < n) *(float2*)&dst[i0g * DH + j0c] = make_float2(C[nt][0], C[nt][1]);
                if (i1g < n) *(float2*)&dst[i1g * DH + j0c] = make_float2(C[nt][2], C[nt][3]);
            }
        }
    }
}

// =====================================================================
// Output: out = h @ out_w + out_b   ([N,64] @ [64,128])
// =====================================================================
__global__ void __launch_bounds__(256, 4)
k_out(const float* __restrict__ ow, const float* __restrict__ ob,
      float* __restrict__ out, int n) {
    extern __shared__ float sm[];
    float* As = sm;            // [64][64]
    float* Ws = sm + 64 * DH;  // [64][128]
    int t = threadIdx.x;
    int base = blockIdx.x * 64;

    #pragma unroll
    for (int it = 0; it < 4; it++) {
        int q = it * 256 + t;
        int i = q >> 4, j4 = (q & 15) * 4;
        float4 v = make_float4(0.f, 0.f, 0.f, 0.f);
        if (base + i < n) v = *(const float4*)&g_h[(base + i) * DH + j4];
        *(float4*)&As[i * DH + j4] = v;
    }
    #pragma unroll
    for (int it = 0; it < 8; it++) {
        int q = it * 256 + t;
        int k = q >> 5, j4 = (q & 31) * 4;
        *(float4*)&Ws[k * 128 + j4] = *(const float4*)&ow[k * 128 + j4];
    }
    __syncthreads();

    int tx = t & 31, ty = t >> 5;
    int j0 = tx * 4, i0 = ty * 8;
    float acc[8][4];
    #pragma unroll
    for (int r = 0; r < 8; r++) {
        acc[r][0] = ob[j0 + 0]; acc[r][1] = ob[j0 + 1];
        acc[r][2] = ob[j0 + 2]; acc[r][3] = ob[j0 + 3];
    }

    GEMM_8x4(As, i0, Ws, 128, acc)

    #pragma unroll
    for (int r = 0; r < 8; r++) {
        int i = base + i0 + r;
        if (i < n)
            *(float4*)&out[i * 128 + j0] =
                make_float4(acc[r][0], acc[r][1], acc[r][2], acc[r][3]);
    }
}

// =====================================================================
// Launcher
// =====================================================================
extern "C" void kernel_launch(void* const* d_in, const int* in_sizes, int n_in,
                              void* d_out, int out_size) {
    const float* x      = (const float*)d_in[0];
    const int*   ei     = (const int*)  d_in[1];
    const float* in_w   = (const float*)d_in[2];
    const float* in_b   = (const float*)d_in[3];
    const float* msg_w1 = (const float*)d_in[4];
    const float* msg_b1 = (const float*)d_in[5];
    const float* msg_w2 = (const float*)d_in[6];
    const float* msg_b2 = (const float*)d_in[7];
    const float* upd_w1 = (const float*)d_in[8];
    const float* upd_b1 = (const float*)d_in[9];
    const float* upd_w2 = (const float*)d_in[10];
    const float* upd_b2 = (const float*)d_in[11];
    const float* out_w  = (const float*)d_in[12];
    const float* out_b  = (const float*)d_in[13];

    int n = in_sizes[0] / 3;
    int e = in_sizes[1] / 2;
    const int* row = ei;
    const int* col = ei + e;

    const int SMEM_UPD = (128 * APS + 32 * ARS + 192) * 4;   // 52,992 B
    const int SMEM_OUT = (64 * DH + 64 * 128) * 4;           // 49152

    cudaFuncSetAttribute(k_update, cudaFuncAttributeMaxDynamicSharedMemorySize, SMEM_UPD);
    cudaFuncSetAttribute(k_out,    cudaFuncAttributeMaxDynamicSharedMemorySize, SMEM_OUT);

    // build CSR (sorted by dst) once; reused by all 3 layers
    int nbn = (n + 255) / 256;
    int ebq = (e + 4 * 256 - 1) / (4 * 256);
    k_zero_hist<<<nbn, 256>>>(n);
    k_hist<<<ebq, 256>>>(col, e);
    k_blocksum<<<nbn, 256>>>(n);
    k_offsets<<<nbn, 256>>>(n, e);
    k_scatter<<<ebq, 256>>>(row, col, e);

    k_prep_all<<<4, 256>>>(msg_w2, upd_w1, msg_b2, msg_w1, in_w, in_b);
    k_input<<<(n * DH + 255) / 256, 256>>>(x, in_w, in_b, n);

    int nb128 = (n + 127) / 128;
    for (int l = 0; l < 3; l++) {
        k_agg<<<(n + 15) / 16, 256>>>(msg_b1 + l * DH, n);
        const float* w1n = (l < 2) ? (msg_w1 + (l + 1) * 2 * DH * DH) : nullptr;
        k_update<<<nb128, 256, SMEM_UPD>>>(upd_w1 + l * 2 * DH * DH, upd_b1 + l * DH,
                                           upd_w2 + l * DH * DH, upd_b2 + l * DH,
                                           l, n, w1n);
    }
    k_out<<<(n + 63) / 64, 256, SMEM_OUT>>>(out_w, out_b, (float*)d_out, n);
}

// round 15
// speedup vs baseline: 1.0016x; 1.0016x over previous
#include <cuda_runtime.h>

#define NN 50000
#define EE 800000
#define DH 64
#define APS 68    // f32 A-tile row stride (conflict-free 32-bit frag loads)
#define ARS 136   // (hi,lo)-pair W-tile row stride

// ---- scratch (device globals; no allocation allowed) ----
__device__ float g_h[NN * DH];
__device__ float g_P[NN * DH];
__device__ float g_Q[NN * DH];
__device__ float g_aggH[NN * DH];
__device__ float g_W2U[3 * DH * DH];   // W2 @ U1b per layer
__device__ float g_b2U[3 * DH];        // b2 @ U1b per layer
__device__ float g_CWP[3 * DH];        // in_w @ W1a[0]
__device__ float g_CWQ[3 * DH];        // in_w @ W1b[0]
__device__ float g_cbP[DH];
__device__ float g_cbQ[DH];
__device__ int   g_hist[NN];
__device__ int   g_bsum[256];
__device__ int   g_off[NN + 1];
__device__ int   g_cur[NN];
__device__ int   g_rows[EE];

// ---- tf32 helpers ----
__device__ __forceinline__ void dec2(float a, float& hi, float& lo) {
    unsigned int hb;
    asm("cvt.rna.tf32.f32 %0, %1;" : "=r"(hb) : "f"(a));
    hi = __uint_as_float(hb);
    float r = a - hi;
    unsigned int lb;
    asm("cvt.rna.tf32.f32 %0, %1;" : "=r"(lb) : "f"(r));
    lo = __uint_as_float(lb);
}

#define MMA(c0, c1, c2, c3, a0, a1, a2, a3, b0, b1)                          \
    asm volatile("mma.sync.aligned.m16n8k8.row.col.f32.tf32.tf32.f32 "       \
                 "{%0,%1,%2,%3}, {%4,%5,%6,%7}, {%8,%9}, {%0,%1,%2,%3};"     \
                 : "+f"(c0), "+f"(c1), "+f"(c2), "+f"(c3)                    \
                 : "r"(a0), "r"(a1), "r"(a2), "r"(a3), "r"(b0), "r"(b1))

// stage 128x64 activation tile as PLAIN f32, row stride APS
#define STAGE_A(SRC)                                                         \
    _Pragma("unroll")                                                        \
    for (int it_ = 0; it_ < 8; it_++) {                                      \
        int q_ = it_ * 256 + t;                                              \
        int i_ = q_ >> 4, j4_ = (q_ & 15) * 4;                               \
        float4 v_ = make_float4(0.f, 0.f, 0.f, 0.f);                         \
        if (base + i_ < n) v_ = *(const float4*)&(SRC)[(base + i_) * DH + j4_]; \
        *(float4*)&As[i_ * APS + j4_] = v_;                                  \
    }

// stage 64x64 weight, decomposed (hi,lo) pairs, k-major rows (stride ARS)
#define STAGE_W(SRC)                                                         \
    _Pragma("unroll")                                                        \
    for (int it_ = 0; it_ < 4; it_++) {                                      \
        int q_ = it_ * 256 + t;                                              \
        int k_ = q_ >> 4, j4_ = (q_ & 15) * 4;                               \
        float4 v_ = *(const float4*)&(SRC)[k_ * DH + j4_];                   \
        float h0_, l0_, h1_, l1_;                                            \
        dec2(v_.x, h0_, l0_); dec2(v_.y, h1_, l1_);                          \
        *(float4*)&WHL[k_ * ARS + 2 * j4_] = make_float4(h0_, l0_, h1_, l1_); \
        dec2(v_.z, h0_, l0_); dec2(v_.w, h1_, l1_);                          \
        *(float4*)&WHL[k_ * ARS + 2 * j4_ + 4] = make_float4(h0_, l0_, h1_, l1_); \
    }

// one 128x64x64 GEMM pass via 3xTF32 mma; A decomposed on the fly.
// A frag banks: (4*gq + t4) mod 32 -> all-distinct, conflict-free LDS.32.
#define MMA_PASS(ACC)                                                        \
    _Pragma("unroll 2")                                                      \
    for (int k0_ = 0; k0_ < 64; k0_ += 8) {                                  \
        float a00_ = As[(row0 + gq) * APS + k0_ + t4];                       \
        float a10_ = As[(row0 + gq + 8) * APS + k0_ + t4];                   \
        float a01_ = As[(row0 + gq) * APS + k0_ + t4 + 4];                   \
        float a11_ = As[(row0 + gq + 8) * APS + k0_ + t4 + 4];               \
        float h_, l_;                                                        \
        dec2(a00_, h_, l_);                                                  \
        unsigned ah0 = __float_as_uint(h_), al0 = __float_as_uint(l_);       \
        dec2(a10_, h_, l_);                                                  \
        unsigned ah1 = __float_as_uint(h_), al1 = __float_as_uint(l_);       \
        dec2(a01_, h_, l_);                                                  \
        unsigned ah2 = __float_as_uint(h_), al2 = __float_as_uint(l_);       \
        dec2(a11_, h_, l_);                                                  \
        unsigned ah3 = __float_as_uint(h_), al3 = __float_as_uint(l_);       \
        _Pragma("unroll")                                                    \
        for (int nt_ = 0; nt_ < 8; nt_++) {                                  \
            float2 fb0 = *(const float2*)&WHL[(k0_ + t4) * ARS + 2 * (nt_ * 8 + gq)];     \
            float2 fb1 = *(const float2*)&WHL[(k0_ + t4 + 4) * ARS + 2 * (nt_ * 8 + gq)]; \
            unsigned bh0 = __float_as_uint(fb0.x), bl0 = __float_as_uint(fb0.y); \
            unsigned bh1 = __float_as_uint(fb1.x), bl1 = __float_as_uint(fb1.y); \
            MMA(ACC[nt_][0], ACC[nt_][1], ACC[nt_][2], ACC[nt_][3],          \
                ah0, ah1, ah2, ah3, bh0, bh1);                               \
            MMA(ACC[nt_][0], ACC[nt_][1], ACC[nt_][2], ACC[nt_][3],          \
                ah0, ah1, ah2, ah3, bl0, bl1);                               \
            MMA(ACC[nt_][0], ACC[nt_][1], ACC[nt_][2], ACC[nt_][3],          \
                al0, al1, al2, al3, bh0, bh1);                               \
        }                                                                    \
    }

// classic f32 macro (k_out only)
#define GEMM_8x4(AS, I0, WS_PTR, WSTRIDE, ACC)                                  \
    _Pragma("unroll 4")                                                          \
    for (int k0 = 0; k0 < 64; k0 += 4) {                                         \
        float4 w0 = *(const float4*)&(WS_PTR)[(k0 + 0) * (WSTRIDE) + j0];        \
        float4 w1 = *(const float4*)&(WS_PTR)[(k0 + 1) * (WSTRIDE) + j0];        \
        float4 w2 = *(const float4*)&(WS_PTR)[(k0 + 2) * (WSTRIDE) + j0];        \
        float4 w3 = *(const float4*)&(WS_PTR)[(k0 + 3) * (WSTRIDE) + j0];        \
        _Pragma("unroll")                                                        \
        for (int r = 0; r < 8; r++) {                                            \
            float4 a4 = *(const float4*)&(AS)[((I0) + r) * DH + k0];             \
            ACC[r][0] = fmaf(a4.x, w0.x, ACC[r][0]);                             \
            ACC[r][1] = fmaf(a4.x, w0.y, ACC[r][1]);                             \
            ACC[r][2] = fmaf(a4.x, w0.z, ACC[r][2]);                             \
            ACC[r][3] = fmaf(a4.x, w0.w, ACC[r][3]);                             \
            ACC[r][0] = fmaf(a4.y, w1.x, ACC[r][0]);                             \
            ACC[r][1] = fmaf(a4.y, w1.y, ACC[r][1]);                             \
            ACC[r][2] = fmaf(a4.y, w1.z, ACC[r][2]);                             \
            ACC[r][3] = fmaf(a4.y, w1.w, ACC[r][3]);                             \
            ACC[r][0] = fmaf(a4.z, w2.x, ACC[r][0]);                             \
            ACC[r][1] = fmaf(a4.z, w2.y, ACC[r][1]);                             \
            ACC[r][2] = fmaf(a4.z, w2.z, ACC[r][2]);                             \
            ACC[r][3] = fmaf(a4.z, w2.w, ACC[r][3]);                             \
            ACC[r][0] = fmaf(a4.w, w3.x, ACC[r][0]);                             \
            ACC[r][1] = fmaf(a4.w, w3.y, ACC[r][1]);                             \
            ACC[r][2] = fmaf(a4.w, w3.z, ACC[r][2]);                             \
            ACC[r][3] = fmaf(a4.w, w3.w, ACC[r][3]);                             \
        }                                                                        \
    }

// =====================================================================
// Fused input: h = x@in_w + in_b ; P0 = x@CWP + cbP ; Q0 = x@CWQ + cbQ
// =====================================================================
__global__ void k_input(const float* __restrict__ x, const float* __restrict__ w,
                        const float* __restrict__ b, int n) {
    int t = blockIdx.x * blockDim.x + threadIdx.x;
    if (t >= n * DH) return;
    int i = t / DH, j = t % DH;
    float x0 = x[i * 3 + 0], x1 = x[i * 3 + 1], x2 = x[i * 3 + 2];
    g_h[t] = fmaf(x0, w[0 * DH + j], fmaf(x1, w[1 * DH + j],
             fmaf(x2, w[2 * DH + j], b[j])));
    g_P[t] = fmaf(x0, g_CWP[0 * DH + j], fmaf(x1, g_CWP[1 * DH + j],
             fmaf(x2, g_CWP[2 * DH + j], g_cbP[j])));
    g_Q[t] = fmaf(x0, g_CWQ[0 * DH + j], fmaf(x1, g_CWQ[1 * DH + j],
             fmaf(x2, g_CWQ[2 * DH + j], g_cbQ[j])));
}

// =====================================================================
// Counting sort of edges by destination (built once, used 3 layers)
// hist/scatter batched 4 edges/thread (MLP 4)
// =====================================================================
__global__ void k_zero_hist(int n) {
    int t = blockIdx.x * blockDim.x + threadIdx.x;
    if (t < n) g_hist[t] = 0;
}
__global__ void k_hist(const int* __restrict__ col, int e) {
    int b = (blockIdx.x * blockDim.x + threadIdx.x) * 4;
    if (b + 3 < e) {
        int4 c = *(const int4*)&col[b];
        atomicAdd(&g_hist[c.x], 1);
        atomicAdd(&g_hist[c.y], 1);
        atomicAdd(&g_hist[c.z], 1);
        atomicAdd(&g_hist[c.w], 1);
    } else {
        for (int i = b; i < e; i++) atomicAdd(&g_hist[col[i]], 1);
    }
}
__global__ void k_blocksum(int n) {
    __shared__ int ss[256];
    int t = threadIdx.x, i = blockIdx.x * 256 + t;
    ss[t] = (i < n) ? g_hist[i] : 0;
    __syncthreads();
    for (int o = 128; o > 0; o >>= 1) {
        if (t < o) ss[t] += ss[t + o];
        __syncthreads();
    }
    if (t == 0) g_bsum[blockIdx.x] = ss[0];
}
__global__ void k_offsets(int n, int e) {
    __shared__ int ss[256];
    int t = threadIdx.x, i = blockIdx.x * 256 + t;
    ss[t] = (t < blockIdx.x) ? g_bsum[t] : 0;
    __syncthreads();
    for (int o = 128; o > 0; o >>= 1) {
        if (t < o) ss[t] += ss[t + o];
        __syncthreads();
    }
    int bpre = ss[0];
    __syncthreads();
    int h = (i < n) ? g_hist[i] : 0;
    ss[t] = h;
    __syncthreads();
    for (int o = 1; o < 256; o <<= 1) {
        int v = (t >= o) ? ss[t - o] : 0;
        __syncthreads();
        ss[t] += v;
        __syncthreads();
    }
    int excl = ss[t] - h + bpre;
    if (i < n) {
        g_off[i] = excl; g_cur[i] = excl;
        if (i == n - 1) g_off[n] = e;
    }
}
__global__ void k_scatter(const int* __restrict__ row, const int* __restrict__ col,
                          int e) {
    int b = (blockIdx.x * blockDim.x + threadIdx.x) * 4;
    if (b + 3 < e) {
        int4 c = *(const int4*)&col[b];
        int4 r = *(const int4*)&row[b];
        int p0 = atomicAdd(&g_cur[c.x], 1);
        int p1 = atomicAdd(&g_cur[c.y], 1);
        int p2 = atomicAdd(&g_cur[c.z], 1);
        int p3 = atomicAdd(&g_cur[c.w], 1);
        g_rows[p0] = r.x; g_rows[p1] = r.y;
        g_rows[p2] = r.z; g_rows[p3] = r.w;
    } else {
        for (int i = b; i < e; i++) {
            int pos = atomicAdd(&g_cur[col[i]], 1);
            g_rows[pos] = row[i];
        }
    }
}

// =====================================================================
// Precompute: blocks 0..2 -> W2U[l], b2U[l]; block 3 -> input composites
// =====================================================================
__global__ void k_prep_all(const float* __restrict__ msg_w2,
                           const float* __restrict__ upd_w1,
                           const float* __restrict__ msg_b2,
                           const float* __restrict__ msg_w1,
                           const float* __restrict__ in_w,
                           const float* __restrict__ in_b) {
    int t = threadIdx.x;
    if (blockIdx.x < 3) {
        int l = blockIdx.x;
        const float* w2  = msg_w2 + l * DH * DH;
        const float* u1b = upd_w1 + l * 2 * DH * DH + DH * DH;
        const float* b2  = msg_b2 + l * DH;
        __shared__ __align__(16) float W2s[DH * DH];
        __shared__ __align__(16) float U1s[DH * DH];
        __shared__ float b2s[DH];
        for (int q = t; q < DH * DH / 4; q += 256) {
            *(float4*)&W2s[q * 4] = *(const float4*)&w2[q * 4];
            *(float4*)&U1s[q * 4] = *(const float4*)&u1b[q * 4];
        }
        if (t < DH) b2s[t] = b2[t];
        __syncthreads();
        for (int idx = t; idx < DH * DH; idx += 256) {
            int k = idx >> 6, j = idx & 63;
            float s = 0.f;
            #pragma unroll 8
            for (int m = 0; m < DH; m++) s = fmaf(W2s[k * DH + m], U1s[m * DH + j], s);
            g_W2U[l * DH * DH + idx] = s;
        }
        if (t < DH) {
            float s = 0.f;
            #pragma unroll 8
            for (int m = 0; m < DH; m++) s = fmaf(b2s[m], U1s[m * DH + t], s);
            g_b2U[l * DH + t] = s;
        }
    } else {
        __shared__ __align__(16) float W1s[2 * DH * DH];
        __shared__ float iws[3 * DH];
        __shared__ float ibs[DH];
        for (int q = t; q < 2 * DH * DH / 4; q += 256)
            *(float4*)&W1s[q * 4] = *(const float4*)&msg_w1[q * 4];
        if (t < 3 * DH) iws[t] = in_w[t];
        if (t < DH) ibs[t] = in_b[t];
        __syncthreads();
        for (int idx = t; idx < 3 * DH; idx += 256) {
            int r = idx >> 6, j = idx & 63;
            float sp = 0.f, sq = 0.f;
            #pragma unroll 8
            for (int k = 0; k < DH; k++) {
                float iv = iws[r * DH + k];
                sp = fmaf(iv, W1s[k * DH + j], sp);
                sq = fmaf(iv, W1s[(DH + k) * DH + j], sq);
            }
            g_CWP[idx] = sp; g_CWQ[idx] = sq;
        }
        if (t < DH) {
            float sp = 0.f, sq = 0.f;
            #pragma unroll 8
            for (int k = 0; k < DH; k++) {
                sp = fmaf(ibs[k], W1s[k * DH + t], sp);
                sq = fmaf(ibs[k], W1s[(DH + k) * DH + t], sq);
            }
            g_cbP[t] = sp; g_cbQ[t] = sq;
        }
    }
}

// =====================================================================
// CSR aggregation: aggH[v] = sum_{e: dst=v} relu(P[src_e] + Q[v] + b1)
// =====================================================================
__global__ void __launch_bounds__(256)
k_agg(const float* __restrict__ b1, int n) {
    int node = blockIdx.x * 16 + (threadIdx.x >> 4);
    int l4 = (threadIdx.x & 15) * 4;
    if (node >= n) return;
    int s = g_off[node], en = g_off[node + 1];
    float4 q = *(const float4*)&g_Q[node * DH + l4];
    float4 b = *(const float4*)&b1[l4];
    q.x += b.x; q.y += b.y; q.z += b.z; q.w += b.w;
    float4 acc = make_float4(0.f, 0.f, 0.f, 0.f);
    int e = s;
    for (; e + 4 <= en; e += 4) {
        int r0 = __ldg(&g_rows[e + 0]);
        int r1 = __ldg(&g_rows[e + 1]);
        int r2 = __ldg(&g_rows[e + 2]);
        int r3 = __ldg(&g_rows[e + 3]);
        float4 p0 = *(const float4*)&g_P[r0 * DH + l4];
        float4 p1 = *(const float4*)&g_P[r1 * DH + l4];
        float4 p2 = *(const float4*)&g_P[r2 * DH + l4];
        float4 p3 = *(const float4*)&g_P[r3 * DH + l4];
        acc.x += fmaxf(p0.x + q.x, 0.f) + fmaxf(p1.x + q.x, 0.f)
               + fmaxf(p2.x + q.x, 0.f) + fmaxf(p3.x + q.x, 0.f);
        acc.y += fmaxf(p0.y + q.y, 0.f) + fmaxf(p1.y + q.y, 0.f)
               + fmaxf(p2.y + q.y, 0.f) + fmaxf(p3.y + q.y, 0.f);
        acc.z += fmaxf(p0.z + q.z, 0.f) + fmaxf(p1.z + q.z, 0.f)
               + fmaxf(p2.z + q.z, 0.f) + fmaxf(p3.z + q.z, 0.f);
        acc.w += fmaxf(p0.w + q.w, 0.f) + fmaxf(p1.w + q.w, 0.f)
               + fmaxf(p2.w + q.w, 0.f) + fmaxf(p3.w + q.w, 0.f);
    }
    for (; e < en; e++) {
        int rr = __ldg(&g_rows[e]);
        float4 p = *(const float4*)&g_P[rr * DH + l4];
        acc.x += fmaxf(p.x + q.x, 0.f);
        acc.y += fmaxf(p.y + q.y, 0.f);
        acc.z += fmaxf(p.z + q.z, 0.f);
        acc.w += fmaxf(p.w + q.w, 0.f);
    }
    *(float4*)&g_aggH[node * DH + l4] = acc;
}

// =====================================================================
// Node update via 3xTF32 mma (A f32 in smem, decomposed at frag load)
// + next-layer P/Q epilogue.  occ 3 (smem ~70KB).  [R12 champion form]
// =====================================================================
__global__ void __launch_bounds__(256, 3)
k_update(const float* __restrict__ u1a, const float* __restrict__ ub1,
         const float* __restrict__ u2, const float* __restrict__ ub2,
         int l, int n, const float* __restrict__ w1_next) {
    extern __shared__ float sm[];
    float* As   = sm;                 // [128][APS] plain f32
    float* WHL  = sm + 128 * APS;     // [64][ARS]  k-major (hi,lo) pairs
    float* ub1s = WHL + 64 * ARS;
    float* ub2s = ub1s + 64;
    float* b2Us = ub2s + 64;
    int t = threadIdx.x;
    int w = t >> 5, lane = t & 31;
    int gq = lane >> 2, t4 = lane & 3;
    int base = blockIdx.x * 128;
    int row0 = w * 16;

    if (t < 64) { ub1s[t] = ub1[t]; ub2s[t] = ub2[t]; b2Us[t] = g_b2U[l * DH + t]; }

    float C[8][4];
    #pragma unroll
    for (int nt = 0; nt < 8; nt++)
        C[nt][0] = C[nt][1] = C[nt][2] = C[nt][3] = 0.f;

    // passes 0,1: h@U1a + aggH@W2U (accumulated together)
    for (int pass = 0; pass < 2; pass++) {
        __syncthreads();
        const float* a_src = pass ? g_aggH : g_h;
        const float* wsrc  = pass ? (g_W2U + l * DH * DH) : u1a;
        STAGE_A(a_src)
        STAGE_W(wsrc)
        __syncthreads();
        MMA_PASS(C)
    }
    __syncthreads();

    // epilogue 1: hid = relu(pre + deg*b2U + ub1) -> As (f32); stage U2
    {
        int i0g = base + row0 + gq, i1g = i0g + 8;
        float dg0 = (i0g < n) ? (float)(g_off[i0g + 1] - g_off[i0g]) : 0.f;
        float dg1 = (i1g < n) ? (float)(g_off[i1g + 1] - g_off[i1g]) : 0.f;
        #pragma unroll
        for (int nt = 0; nt < 8; nt++) {
            int j0c = nt * 8 + 2 * t4, j1c = j0c + 1;
            float v00 = fmaxf(C[nt][0] + dg0 * b2Us[j0c] + ub1s[j0c], 0.f);
            float v01 = fmaxf(C[nt][1] + dg0 * b2Us[j1c] + ub1s[j1c], 0.f);
            float v10 = fmaxf(C[nt][2] + dg1 * b2Us[j0c] + ub1s[j0c], 0.f);
            float v11 = fmaxf(C[nt][3] + dg1 * b2Us[j1c] + ub1s[j1c], 0.f);
            *(float2*)&As[(row0 + gq) * APS + j0c] = make_float2(v00, v01);
            *(float2*)&As[(row0 + gq + 8) * APS + j0c] = make_float2(v10, v11);
        }
    }
    STAGE_W(u2)
    __syncthreads();

    #pragma unroll
    for (int nt = 0; nt < 8; nt++)
        C[nt][0] = C[nt][1] = C[nt][2] = C[nt][3] = 0.f;
    MMA_PASS(C)
    __syncthreads();

    // epilogue 2: h = relu(C + ub2) -> gmem (+ As if P/Q needed)
    {
        int i0g = base + row0 + gq, i1g = i0g + 8;
        #pragma unroll
        for (int nt = 0; nt < 8; nt++) {
            int j0c = nt * 8 + 2 * t4, j1c = j0c + 1;
            float v00 = fmaxf(C[nt][0] + ub2s[j0c], 0.f);
            float v01 = fmaxf(C[nt][1] + ub2s[j1c], 0.f);
            float v10 = fmaxf(C[nt][2] + ub2s[j0c], 0.f);
            float v11 = fmaxf(C[nt][3] + ub2s[j1c], 0.f);
            if (i0g < n) *(float2*)&g_h[i0g * DH + j0c] = make_float2(v00, v01);
            if (i1g < n) *(float2*)&g_h[i1g * DH + j0c] = make_float2(v10, v11);
            if (w1_next) {
                *(float2*)&As[(row0 + gq) * APS + j0c] = make_float2(v00, v01);
                *(float2*)&As[(row0 + gq + 8) * APS + j0c] = make_float2(v10, v11);
            }
        }
    }

    if (w1_next) {
        for (int pass = 0; pass < 2; pass++) {
            __syncthreads();
            STAGE_W(w1_next + pass * 64 * DH)
            __syncthreads();
            #pragma unroll
            for (int nt = 0; nt < 8; nt++)
                C[nt][0] = C[nt][1] = C[nt][2] = C[nt][3] = 0.f;
            MMA_PASS(C)
            float* dst = pass ? g_Q : g_P;
            int i0g = base + row0 + gq, i1g = i0g + 8;
            #pragma unroll
            for (int nt = 0; nt < 8; nt++) {
                int j0c = nt * 8 + 2 * t4;
                if (i0g < n) *(float2*)&dst[i0g * DH + j0c] = make_float2(C[nt][0], C[nt][1]);
                if (i1g < n) *(float2*)&dst[i1g * DH + j0c] = make_float2(C[nt][2], C[nt][3]);
            }
        }
    }
}

// =====================================================================
// Output: out = h @ out_w + out_b   ([N,64] @ [64,128])
// =====================================================================
__global__ void __launch_bounds__(256, 4)
k_out(const float* __restrict__ ow, const float* __restrict__ ob,
      float* __restrict__ out, int n) {
    extern __shared__ float sm[];
    float* As = sm;            // [64][64]
    float* Ws = sm + 64 * DH;  // [64][128]
    int t = threadIdx.x;
    int base = blockIdx.x * 64;

    #pragma unroll
    for (int it = 0; it < 4; it++) {
        int q = it * 256 + t;
        int i = q >> 4, j4 = (q & 15) * 4;
        float4 v = make_float4(0.f, 0.f, 0.f, 0.f);
        if (base + i < n) v = *(const float4*)&g_h[(base + i) * DH + j4];
        *(float4*)&As[i * DH + j4] = v;
    }
    #pragma unroll
    for (int it = 0; it < 8; it++) {
        int q = it * 256 + t;
        int k = q >> 5, j4 = (q & 31) * 4;
        *(float4*)&Ws[k * 128 + j4] = *(const float4*)&ow[k * 128 + j4];
    }
    __syncthreads();

    int tx = t & 31, ty = t >> 5;
    int j0 = tx * 4, i0 = ty * 8;
    float acc[8][4];
    #pragma unroll
    for (int r = 0; r < 8; r++) {
        acc[r][0] = ob[j0 + 0]; acc[r][1] = ob[j0 + 1];
        acc[r][2] = ob[j0 + 2]; acc[r][3] = ob[j0 + 3];
    }

    GEMM_8x4(As, i0, Ws, 128, acc)

    #pragma unroll
    for (int r = 0; r < 8; r++) {
        int i = base + i0 + r;
        if (i < n)
            *(float4*)&out[i * 128 + j0] =
                make_float4(acc[r][0], acc[r][1], acc[r][2], acc[r][3]);
    }
}

// =====================================================================
// Launcher
// =====================================================================
extern "C" void kernel_launch(void* const* d_in, const int* in_sizes, int n_in,
                              void* d_out, int out_size) {
    const float* x      = (const float*)d_in[0];
    const int*   ei     = (const int*)  d_in[1];
    const float* in_w   = (const float*)d_in[2];
    const float* in_b   = (const float*)d_in[3];
    const float* msg_w1 = (const float*)d_in[4];
    const float* msg_b1 = (const float*)d_in[5];
    const float* msg_w2 = (const float*)d_in[6];
    const float* msg_b2 = (const float*)d_in[7];
    const float* upd_w1 = (const float*)d_in[8];
    const float* upd_b1 = (const float*)d_in[9];
    const float* upd_w2 = (const float*)d_in[10];
    const float* upd_b2 = (const float*)d_in[11];
    const float* out_w  = (const float*)d_in[12];
    const float* out_b  = (const float*)d_in[13];

    int n = in_sizes[0] / 3;
    int e = in_sizes[1] / 2;
    const int* row = ei;
    const int* col = ei + e;

    const int SMEM_UPD = (128 * APS + 64 * ARS + 192) * 4;   // 70,400 B
    const int SMEM_OUT = (64 * DH + 64 * 128) * 4;           // 49152

    cudaFuncSetAttribute(k_update, cudaFuncAttributeMaxDynamicSharedMemorySize, SMEM_UPD);
    cudaFuncSetAttribute(k_out,    cudaFuncAttributeMaxDynamicSharedMemorySize, SMEM_OUT);

    // build CSR (sorted by dst) once; reused by all 3 layers
    int nbn = (n + 255) / 256;
    int ebq = (e + 4 * 256 - 1) / (4 * 256);
    k_zero_hist<<<nbn, 256>>>(n);
    k_hist<<<ebq, 256>>>(col, e);
    k_blocksum<<<nbn, 256>>>(n);
    k_offsets<<<nbn, 256>>>(n, e);
    k_scatter<<<ebq, 256>>>(row, col, e);

    k_prep_all<<<4, 256>>>(msg_w2, upd_w1, msg_b2, msg_w1, in_w, in_b);
    k_input<<<(n * DH + 255) / 256, 256>>>(x, in_w, in_b, n);

    int nb128 = (n + 127) / 128;
    for (int l = 0; l < 3; l++) {
        k_agg<<<(n + 15) / 16, 256>>>(msg_b1 + l * DH, n);
        const float* w1n = (l < 2) ? (msg_w1 + (l + 1) * 2 * DH * DH) : nullptr;
        k_update<<<nb128, 256, SMEM_UPD>>>(upd_w1 + l * 2 * DH * DH, upd_b1 + l * DH,
                                           upd_w2 + l * DH * DH, upd_b2 + l * DH,
                                           l, n, w1n);
    }
    k_out<<<(n + 63) / 64, 256, SMEM_OUT>>>(out_w, out_b, (float*)d_out, n);
}

// round 16
// speedup vs baseline: 1.0157x; 1.0141x over previous
#include <cuda_runtime.h>

#define NN 50000
#define EE 800000
#define DH 64
#define APS 68    // f32 A-tile row stride (conflict-free 32-bit frag loads)
#define ARS 136   // (hi,lo)-pair W-tile row stride

// ---- scratch (device globals; no allocation allowed) ----
__device__ float g_h[NN * DH];
__device__ float g_P[NN * DH];
__device__ float g_Q[NN * DH];
__device__ float g_aggH[NN * DH];
__device__ float g_W2U[3 * DH * DH];   // W2 @ U1b per layer
__device__ float g_b2U[3 * DH];        // b2 @ U1b per layer
__device__ float g_CWP[3 * DH];        // in_w @ W1a[0]
__device__ float g_CWQ[3 * DH];        // in_w @ W1b[0]
__device__ float g_cbP[DH];
__device__ float g_cbQ[DH];
__device__ int   g_hist[NN];           // zero-initialized at load; re-zeroed by k_out
__device__ int   g_bsum[256];
__device__ int   g_off[NN + 1];
__device__ int   g_cur[NN];
__device__ int   g_rows[EE];

// ---- tf32 helpers ----
__device__ __forceinline__ void dec2(float a, float& hi, float& lo) {
    unsigned int hb;
    asm("cvt.rna.tf32.f32 %0, %1;" : "=r"(hb) : "f"(a));
    hi = __uint_as_float(hb);
    float r = a - hi;
    unsigned int lb;
    asm("cvt.rna.tf32.f32 %0, %1;" : "=r"(lb) : "f"(r));
    lo = __uint_as_float(lb);
}

#define MMA(c0, c1, c2, c3, a0, a1, a2, a3, b0, b1)                          \
    asm volatile("mma.sync.aligned.m16n8k8.row.col.f32.tf32.tf32.f32 "       \
                 "{%0,%1,%2,%3}, {%4,%5,%6,%7}, {%8,%9}, {%0,%1,%2,%3};"     \
                 : "+f"(c0), "+f"(c1), "+f"(c2), "+f"(c3)                    \
                 : "r"(a0), "r"(a1), "r"(a2), "r"(a3), "r"(b0), "r"(b1))

// stage 128x64 activation tile as PLAIN f32, row stride APS
#define STAGE_A(SRC)                                                         \
    _Pragma("unroll")                                                        \
    for (int it_ = 0; it_ < 8; it_++) {                                      \
        int q_ = it_ * 256 + t;                                              \
        int i_ = q_ >> 4, j4_ = (q_ & 15) * 4;                               \
        float4 v_ = make_float4(0.f, 0.f, 0.f, 0.f);                         \
        if (base + i_ < n) v_ = *(const float4*)&(SRC)[(base + i_) * DH + j4_]; \
        *(float4*)&As[i_ * APS + j4_] = v_;                                  \
    }

// stage 64x64 weight, decomposed (hi,lo) pairs, k-major rows (stride ARS)
#define STAGE_W(SRC)                                                         \
    _Pragma("unroll")                                                        \
    for (int it_ = 0; it_ < 4; it_++) {                                      \
        int q_ = it_ * 256 + t;                                              \
        int k_ = q_ >> 4, j4_ = (q_ & 15) * 4;                               \
        float4 v_ = *(const float4*)&(SRC)[k_ * DH + j4_];                   \
        float h0_, l0_, h1_, l1_;                                            \
        dec2(v_.x, h0_, l0_); dec2(v_.y, h1_, l1_);                          \
        *(float4*)&WHL[k_ * ARS + 2 * j4_] = make_float4(h0_, l0_, h1_, l1_); \
        dec2(v_.z, h0_, l0_); dec2(v_.w, h1_, l1_);                          \
        *(float4*)&WHL[k_ * ARS + 2 * j4_ + 4] = make_float4(h0_, l0_, h1_, l1_); \
    }

// one 128x64x64 GEMM pass via 3xTF32 mma; A decomposed on the fly.
#define MMA_PASS(ACC)                                                        \
    _Pragma("unroll 2")                                                      \
    for (int k0_ = 0; k0_ < 64; k0_ += 8) {                                  \
        float a00_ = As[(row0 + gq) * APS + k0_ + t4];                       \
        float a10_ = As[(row0 + gq + 8) * APS + k0_ + t4];                   \
        float a01_ = As[(row0 + gq) * APS + k0_ + t4 + 4];                   \
        float a11_ = As[(row0 + gq + 8) * APS + k0_ + t4 + 4];               \
        float h_, l_;                                                        \
        dec2(a00_, h_, l_);                                                  \
        unsigned ah0 = __float_as_uint(h_), al0 = __float_as_uint(l_);       \
        dec2(a10_, h_, l_);                                                  \
        unsigned ah1 = __float_as_uint(h_), al1 = __float_as_uint(l_);       \
        dec2(a01_, h_, l_);                                                  \
        unsigned ah2 = __float_as_uint(h_), al2 = __float_as_uint(l_);       \
        dec2(a11_, h_, l_);                                                  \
        unsigned ah3 = __float_as_uint(h_), al3 = __float_as_uint(l_);       \
        _Pragma("unroll")                                                    \
        for (int nt_ = 0; nt_ < 8; nt_++) {                                  \
            float2 fb0 = *(const float2*)&WHL[(k0_ + t4) * ARS + 2 * (nt_ * 8 + gq)];     \
            float2 fb1 = *(const float2*)&WHL[(k0_ + t4 + 4) * ARS + 2 * (nt_ * 8 + gq)]; \
            unsigned bh0 = __float_as_uint(fb0.x), bl0 = __float_as_uint(fb0.y); \
            unsigned bh1 = __float_as_uint(fb1.x), bl1 = __float_as_uint(fb1.y); \
            MMA(ACC[nt_][0], ACC[nt_][1], ACC[nt_][2], ACC[nt_][3],          \
                ah0, ah1, ah2, ah3, bh0, bh1);                               \
            MMA(ACC[nt_][0], ACC[nt_][1], ACC[nt_][2], ACC[nt_][3],          \
                ah0, ah1, ah2, ah3, bl0, bl1);                               \
            MMA(ACC[nt_][0], ACC[nt_][1], ACC[nt_][2], ACC[nt_][3],          \
                al0, al1, al2, al3, bh0, bh1);                               \
        }                                                                    \
    }

// classic f32 macro (k_out only)
#define GEMM_8x4(AS, I0, WS_PTR, WSTRIDE, ACC)                                  \
    _Pragma("unroll 4")                                                          \
    for (int k0 = 0; k0 < 64; k0 += 4) {                                         \
        float4 w0 = *(const float4*)&(WS_PTR)[(k0 + 0) * (WSTRIDE) + j0];        \
        float4 w1 = *(const float4*)&(WS_PTR)[(k0 + 1) * (WSTRIDE) + j0];        \
        float4 w2 = *(const float4*)&(WS_PTR)[(k0 + 2) * (WSTRIDE) + j0];        \
        float4 w3 = *(const float4*)&(WS_PTR)[(k0 + 3) * (WSTRIDE) + j0];        \
        _Pragma("unroll")                                                        \
        for (int r = 0; r < 8; r++) {                                            \
            float4 a4 = *(const float4*)&(AS)[((I0) + r) * DH + k0];             \
            ACC[r][0] = fmaf(a4.x, w0.x, ACC[r][0]);                             \
            ACC[r][1] = fmaf(a4.x, w0.y, ACC[r][1]);                             \
            ACC[r][2] = fmaf(a4.x, w0.z, ACC[r][2]);                             \
            ACC[r][3] = fmaf(a4.x, w0.w, ACC[r][3]);                             \
            ACC[r][0] = fmaf(a4.y, w1.x, ACC[r][0]);                             \
            ACC[r][1] = fmaf(a4.y, w1.y, ACC[r][1]);                             \
            ACC[r][2] = fmaf(a4.y, w1.z, ACC[r][2]);                             \
            ACC[r][3] = fmaf(a4.y, w1.w, ACC[r][3]);                             \
            ACC[r][0] = fmaf(a4.z, w2.x, ACC[r][0]);                             \
            ACC[r][1] = fmaf(a4.z, w2.y, ACC[r][1]);                             \
            ACC[r][2] = fmaf(a4.z, w2.z, ACC[r][2]);                             \
            ACC[r][3] = fmaf(a4.z, w2.w, ACC[r][3]);                             \
            ACC[r][0] = fmaf(a4.w, w3.x, ACC[r][0]);                             \
            ACC[r][1] = fmaf(a4.w, w3.y, ACC[r][1]);                             \
            ACC[r][2] = fmaf(a4.w, w3.z, ACC[r][2]);                             \
            ACC[r][3] = fmaf(a4.w, w3.w, ACC[r][3]);                             \
        }                                                                        \
    }

// =====================================================================
// Fused input: h = x@in_w + in_b ; P0 = x@CWP + cbP ; Q0 = x@CWQ + cbQ
// =====================================================================
__global__ void k_input(const float* __restrict__ x, const float* __restrict__ w,
                        const float* __restrict__ b, int n) {
    int t = blockIdx.x * blockDim.x + threadIdx.x;
    if (t >= n * DH) return;
    int i = t / DH, j = t % DH;
    float x0 = x[i * 3 + 0], x1 = x[i * 3 + 1], x2 = x[i * 3 + 2];
    g_h[t] = fmaf(x0, w[0 * DH + j], fmaf(x1, w[1 * DH + j],
             fmaf(x2, w[2 * DH + j], b[j])));
    g_P[t] = fmaf(x0, g_CWP[0 * DH + j], fmaf(x1, g_CWP[1 * DH + j],
             fmaf(x2, g_CWP[2 * DH + j], g_cbP[j])));
    g_Q[t] = fmaf(x0, g_CWQ[0 * DH + j], fmaf(x1, g_CWQ[1 * DH + j],
             fmaf(x2, g_CWQ[2 * DH + j], g_cbQ[j])));
}

// =====================================================================
// Counting sort of edges by destination (built once, used 3 layers).
// g_hist is zero on entry: statically zero-initialized before the first
// run, and re-zeroed at the end of k_out on every run thereafter.
// =====================================================================
__global__ void k_hist(const int* __restrict__ col, int e) {
    int t = blockIdx.x * blockDim.x + threadIdx.x;
    if (t < e) atomicAdd(&g_hist[col[t]], 1);
}
__global__ void k_blocksum(int n) {
    __shared__ int ss[256];
    int t = threadIdx.x, i = blockIdx.x * 256 + t;
    ss[t] = (i < n) ? g_hist[i] : 0;
    __syncthreads();
    for (int o = 128; o > 0; o >>= 1) {
        if (t < o) ss[t] += ss[t + o];
        __syncthreads();
    }
    if (t == 0) g_bsum[blockIdx.x] = ss[0];
}
__global__ void k_offsets(int n, int e) {
    __shared__ int ss[256];
    int t = threadIdx.x, i = blockIdx.x * 256 + t;
    ss[t] = (t < blockIdx.x) ? g_bsum[t] : 0;
    __syncthreads();
    for (int o = 128; o > 0; o >>= 1) {
        if (t < o) ss[t] += ss[t + o];
        __syncthreads();
    }
    int bpre = ss[0];
    __syncthreads();
    int h = (i < n) ? g_hist[i] : 0;
    ss[t] = h;
    __syncthreads();
    for (int o = 1; o < 256; o <<= 1) {
        int v = (t >= o) ? ss[t - o] : 0;
        __syncthreads();
        ss[t] += v;
        __syncthreads();
    }
    int excl = ss[t] - h + bpre;
    if (i < n) {
        g_off[i] = excl; g_cur[i] = excl;
        if (i == n - 1) g_off[n] = e;
    }
}
__global__ void k_scatter(const int* __restrict__ row, const int* __restrict__ col,
                          int e) {
    int t = blockIdx.x * blockDim.x + threadIdx.x;
    if (t >= e) return;
    int c = col[t];
    int pos = atomicAdd(&g_cur[c], 1);
    g_rows[pos] = row[t];
}

// =====================================================================
// Precompute: blocks 0..2 -> W2U[l], b2U[l]; block 3 -> input composites
// =====================================================================
__global__ void k_prep_all(const float* __restrict__ msg_w2,
                           const float* __restrict__ upd_w1,
                           const float* __restrict__ msg_b2,
                           const float* __restrict__ msg_w1,
                           const float* __restrict__ in_w,
                           const float* __restrict__ in_b) {
    int t = threadIdx.x;
    if (blockIdx.x < 3) {
        int l = blockIdx.x;
        const float* w2  = msg_w2 + l * DH * DH;
        const float* u1b = upd_w1 + l * 2 * DH * DH + DH * DH;
        const float* b2  = msg_b2 + l * DH;
        __shared__ __align__(16) float W2s[DH * DH];
        __shared__ __align__(16) float U1s[DH * DH];
        __shared__ float b2s[DH];
        for (int q = t; q < DH * DH / 4; q += 256) {
            *(float4*)&W2s[q * 4] = *(const float4*)&w2[q * 4];
            *(float4*)&U1s[q * 4] = *(const float4*)&u1b[q * 4];
        }
        if (t < DH) b2s[t] = b2[t];
        __syncthreads();
        for (int idx = t; idx < DH * DH; idx += 256) {
            int k = idx >> 6, j = idx & 63;
            float s = 0.f;
            #pragma unroll 8
            for (int m = 0; m < DH; m++) s = fmaf(W2s[k * DH + m], U1s[m * DH + j], s);
            g_W2U[l * DH * DH + idx] = s;
        }
        if (t < DH) {
            float s = 0.f;
            #pragma unroll 8
            for (int m = 0; m < DH; m++) s = fmaf(b2s[m], U1s[m * DH + t], s);
            g_b2U[l * DH + t] = s;
        }
    } else {
        __shared__ __align__(16) float W1s[2 * DH * DH];
        __shared__ float iws[3 * DH];
        __shared__ float ibs[DH];
        for (int q = t; q < 2 * DH * DH / 4; q += 256)
            *(float4*)&W1s[q * 4] = *(const float4*)&msg_w1[q * 4];
        if (t < 3 * DH) iws[t] = in_w[t];
        if (t < DH) ibs[t] = in_b[t];
        __syncthreads();
        for (int idx = t; idx < 3 * DH; idx += 256) {
            int r = idx >> 6, j = idx & 63;
            float sp = 0.f, sq = 0.f;
            #pragma unroll 8
            for (int k = 0; k < DH; k++) {
                float iv = iws[r * DH + k];
                sp = fmaf(iv, W1s[k * DH + j], sp);
                sq = fmaf(iv, W1s[(DH + k) * DH + j], sq);
            }
            g_CWP[idx] = sp; g_CWQ[idx] = sq;
        }
        if (t < DH) {
            float sp = 0.f, sq = 0.f;
            #pragma unroll 8
            for (int k = 0; k < DH; k++) {
                sp = fmaf(ibs[k], W1s[k * DH + t], sp);
                sq = fmaf(ibs[k], W1s[(DH + k) * DH + t], sq);
            }
            g_cbP[t] = sp; g_cbQ[t] = sq;
        }
    }
}

// =====================================================================
// CSR aggregation: aggH[v] = sum_{e: dst=v} relu(P[src_e] + Q[v] + b1)
// 16 lanes/node; main loop unroll 8 (MLP 8 on gathers)
// =====================================================================
__global__ void __launch_bounds__(256)
k_agg(const float* __restrict__ b1, int n) {
    int node = blockIdx.x * 16 + (threadIdx.x >> 4);
    int l4 = (threadIdx.x & 15) * 4;
    if (node >= n) return;
    int s = g_off[node], en = g_off[node + 1];
    float4 q = *(const float4*)&g_Q[node * DH + l4];
    float4 b = *(const float4*)&b1[l4];
    q.x += b.x; q.y += b.y; q.z += b.z; q.w += b.w;
    float4 acc = make_float4(0.f, 0.f, 0.f, 0.f);
    int e = s;
    for (; e + 8 <= en; e += 8) {
        int r0 = __ldg(&g_rows[e + 0]);
        int r1 = __ldg(&g_rows[e + 1]);
        int r2 = __ldg(&g_rows[e + 2]);
        int r3 = __ldg(&g_rows[e + 3]);
        int r4 = __ldg(&g_rows[e + 4]);
        int r5 = __ldg(&g_rows[e + 5]);
        int r6 = __ldg(&g_rows[e + 6]);
        int r7 = __ldg(&g_rows[e + 7]);
        float4 p0 = *(const float4*)&g_P[r0 * DH + l4];
        float4 p1 = *(const float4*)&g_P[r1 * DH + l4];
        float4 p2 = *(const float4*)&g_P[r2 * DH + l4];
        float4 p3 = *(const float4*)&g_P[r3 * DH + l4];
        float4 p4 = *(const float4*)&g_P[r4 * DH + l4];
        float4 p5 = *(const float4*)&g_P[r5 * DH + l4];
        float4 p6 = *(const float4*)&g_P[r6 * DH + l4];
        float4 p7 = *(const float4*)&g_P[r7 * DH + l4];
        acc.x += fmaxf(p0.x + q.x, 0.f) + fmaxf(p1.x + q.x, 0.f)
               + fmaxf(p2.x + q.x, 0.f) + fmaxf(p3.x + q.x, 0.f)
               + fmaxf(p4.x + q.x, 0.f) + fmaxf(p5.x + q.x, 0.f)
               + fmaxf(p6.x + q.x, 0.f) + fmaxf(p7.x + q.x, 0.f);
        acc.y += fmaxf(p0.y + q.y, 0.f) + fmaxf(p1.y + q.y, 0.f)
               + fmaxf(p2.y + q.y, 0.f) + fmaxf(p3.y + q.y, 0.f)
               + fmaxf(p4.y + q.y, 0.f) + fmaxf(p5.y + q.y, 0.f)
               + fmaxf(p6.y + q.y, 0.f) + fmaxf(p7.y + q.y, 0.f);
        acc.z += fmaxf(p0.z + q.z, 0.f) + fmaxf(p1.z + q.z, 0.f)
               + fmaxf(p2.z + q.z, 0.f) + fmaxf(p3.z + q.z, 0.f)
               + fmaxf(p4.z + q.z, 0.f) + fmaxf(p5.z + q.z, 0.f)
               + fmaxf(p6.z + q.z, 0.f) + fmaxf(p7.z + q.z, 0.f);
        acc.w += fmaxf(p0.w + q.w, 0.f) + fmaxf(p1.w + q.w, 0.f)
               + fmaxf(p2.w + q.w, 0.f) + fmaxf(p3.w + q.w, 0.f)
               + fmaxf(p4.w + q.w, 0.f) + fmaxf(p5.w + q.w, 0.f)
               + fmaxf(p6.w + q.w, 0.f) + fmaxf(p7.w + q.w, 0.f);
    }
    for (; e < en; e++) {
        int rr = __ldg(&g_rows[e]);
        float4 p = *(const float4*)&g_P[rr * DH + l4];
        acc.x += fmaxf(p.x + q.x, 0.f);
        acc.y += fmaxf(p.y + q.y, 0.f);
        acc.z += fmaxf(p.z + q.z, 0.f);
        acc.w += fmaxf(p.w + q.w, 0.f);
    }
    *(float4*)&g_aggH[node * DH + l4] = acc;
}

// =====================================================================
// Node update via 3xTF32 mma (A f32 in smem, decomposed at frag load)
// + next-layer P/Q epilogue.  occ 3 (smem ~70KB).  [R12 champion form]
// =====================================================================
__global__ void __launch_bounds__(256, 3)
k_update(const float* __restrict__ u1a, const float* __restrict__ ub1,
         const float* __restrict__ u2, const float* __restrict__ ub2,
         int l, int n, const float* __restrict__ w1_next) {
    extern __shared__ float sm[];
    float* As   = sm;                 // [128][APS] plain f32
    float* WHL  = sm + 128 * APS;     // [64][ARS]  k-major (hi,lo) pairs
    float* ub1s = WHL + 64 * ARS;
    float* ub2s = ub1s + 64;
    float* b2Us = ub2s + 64;
    int t = threadIdx.x;
    int w = t >> 5, lane = t & 31;
    int gq = lane >> 2, t4 = lane & 3;
    int base = blockIdx.x * 128;
    int row0 = w * 16;

    if (t < 64) { ub1s[t] = ub1[t]; ub2s[t] = ub2[t]; b2Us[t] = g_b2U[l * DH + t]; }

    float C[8][4];
    #pragma unroll
    for (int nt = 0; nt < 8; nt++)
        C[nt][0] = C[nt][1] = C[nt][2] = C[nt][3] = 0.f;

    // passes 0,1: h@U1a + aggH@W2U (accumulated together)
    for (int pass = 0; pass < 2; pass++) {
        __syncthreads();
        const float* a_src = pass ? g_aggH : g_h;
        const float* wsrc  = pass ? (g_W2U + l * DH * DH) : u1a;
        STAGE_A(a_src)
        STAGE_W(wsrc)
        __syncthreads();
        MMA_PASS(C)
    }
    __syncthreads();

    // epilogue 1: hid = relu(pre + deg*b2U + ub1) -> As (f32); stage U2
    {
        int i0g = base + row0 + gq, i1g = i0g + 8;
        float dg0 = (i0g < n) ? (float)(g_off[i0g + 1] - g_off[i0g]) : 0.f;
        float dg1 = (i1g < n) ? (float)(g_off[i1g + 1] - g_off[i1g]) : 0.f;
        #pragma unroll
        for (int nt = 0; nt < 8; nt++) {
            int j0c = nt * 8 + 2 * t4, j1c = j0c + 1;
            float v00 = fmaxf(C[nt][0] + dg0 * b2Us[j0c] + ub1s[j0c], 0.f);
            float v01 = fmaxf(C[nt][1] + dg0 * b2Us[j1c] + ub1s[j1c], 0.f);
            float v10 = fmaxf(C[nt][2] + dg1 * b2Us[j0c] + ub1s[j0c], 0.f);
            float v11 = fmaxf(C[nt][3] + dg1 * b2Us[j1c] + ub1s[j1c], 0.f);
            *(float2*)&As[(row0 + gq) * APS + j0c] = make_float2(v00, v01);
            *(float2*)&As[(row0 + gq + 8) * APS + j0c] = make_float2(v10, v11);
        }
    }
    STAGE_W(u2)
    __syncthreads();

    #pragma unroll
    for (int nt = 0; nt < 8; nt++)
        C[nt][0] = C[nt][1] = C[nt][2] = C[nt][3] = 0.f;
    MMA_PASS(C)
    __syncthreads();

    // epilogue 2: h = relu(C + ub2) -> gmem (+ As if P/Q needed)
    {
        int i0g = base + row0 + gq, i1g = i0g + 8;
        #pragma unroll
        for (int nt = 0; nt < 8; nt++) {
            int j0c = nt * 8 + 2 * t4, j1c = j0c + 1;
            float v00 = fmaxf(C[nt][0] + ub2s[j0c], 0.f);
            float v01 = fmaxf(C[nt][1] + ub2s[j1c], 0.f);
            float v10 = fmaxf(C[nt][2] + ub2s[j0c], 0.f);
            float v11 = fmaxf(C[nt][3] + ub2s[j1c], 0.f);
            if (i0g < n) *(float2*)&g_h[i0g * DH + j0c] = make_float2(v00, v01);
            if (i1g < n) *(float2*)&g_h[i1g * DH + j0c] = make_float2(v10, v11);
            if (w1_next) {
                *(float2*)&As[(row0 + gq) * APS + j0c] = make_float2(v00, v01);
                *(float2*)&As[(row0 + gq + 8) * APS + j0c] = make_float2(v10, v11);
            }
        }
    }

    if (w1_next) {
        for (int pass = 0; pass < 2; pass++) {
            __syncthreads();
            STAGE_W(w1_next + pass * 64 * DH)
            __syncthreads();
            #pragma unroll
            for (int nt = 0; nt < 8; nt++)
                C[nt][0] = C[nt][1] = C[nt][2] = C[nt][3] = 0.f;
            MMA_PASS(C)
            float* dst = pass ? g_Q : g_P;
            int i0g = base + row0 + gq, i1g = i0g + 8;
            #pragma unroll
            for (int nt = 0; nt < 8; nt++) {
                int j0c = nt * 8 + 2 * t4;
                if (i0g < n) *(float2*)&dst[i0g * DH + j0c] = make_float2(C[nt][0], C[nt][1]);
                if (i1g < n) *(float2*)&dst[i1g * DH + j0c] = make_float2(C[nt][2], C[nt][3]);
            }
        }
    }
}

// =====================================================================
// Output: out = h @ out_w + out_b   ([N,64] @ [64,128])
// Also re-zeros g_hist for the next invocation (graph replay).
// =====================================================================
__global__ void __launch_bounds__(256, 4)
k_out(const float* __restrict__ ow, const float* __restrict__ ob,
      float* __restrict__ out, int n) {
    extern __shared__ float sm[];
    float* As = sm;            // [64][64]
    float* Ws = sm + 64 * DH;  // [64][128]
    int t = threadIdx.x;
    int base = blockIdx.x * 64;

    // fold hist-zeroing for the NEXT run into this grid (grid covers NN)
    int gt = blockIdx.x * 256 + t;
    if (gt < NN) g_hist[gt] = 0;

    #pragma unroll
    for (int it = 0; it < 4; it++) {
        int q = it * 256 + t;
        int i = q >> 4, j4 = (q & 15) * 4;
        float4 v = make_float4(0.f, 0.f, 0.f, 0.f);
        if (base + i < n) v = *(const float4*)&g_h[(base + i) * DH + j4];
        *(float4*)&As[i * DH + j4] = v;
    }
    #pragma unroll
    for (int it = 0; it < 8; it++) {
        int q = it * 256 + t;
        int k = q >> 5, j4 = (q & 31) * 4;
        *(float4*)&Ws[k * 128 + j4] = *(const float4*)&ow[k * 128 + j4];
    }
    __syncthreads();

    int tx = t & 31, ty = t >> 5;
    int j0 = tx * 4, i0 = ty * 8;
    float acc[8][4];
    #pragma unroll
    for (int r = 0; r < 8; r++) {
        acc[r][0] = ob[j0 + 0]; acc[r][1] = ob[j0 + 1];
        acc[r][2] = ob[j0 + 2]; acc[r][3] = ob[j0 + 3];
    }

    GEMM_8x4(As, i0, Ws, 128, acc)

    #pragma unroll
    for (int r = 0; r < 8; r++) {
        int i = base + i0 + r;
        if (i < n)
            *(float4*)&out[i * 128 + j0] =
                make_float4(acc[r][0], acc[r][1], acc[r][2], acc[r][3]);
    }
}

// =====================================================================
// Launcher
// =====================================================================
extern "C" void kernel_launch(void* const* d_in, const int* in_sizes, int n_in,
                              void* d_out, int out_size) {
    const float* x      = (const float*)d_in[0];
    const int*   ei     = (const int*)  d_in[1];
    const float* in_w   = (const float*)d_in[2];
    const float* in_b   = (const float*)d_in[3];
    const float* msg_w1 = (const float*)d_in[4];
    const float* msg_b1 = (const float*)d_in[5];
    const float* msg_w2 = (const float*)d_in[6];
    const float* msg_b2 = (const float*)d_in[7];
    const float* upd_w1 = (const float*)d_in[8];
    const float* upd_b1 = (const float*)d_in[9];
    const float* upd_w2 = (const float*)d_in[10];
    const float* upd_b2 = (const float*)d_in[11];
    const float* out_w  = (const float*)d_in[12];
    const float* out_b  = (const float*)d_in[13];

    int n = in_sizes[0] / 3;
    int e = in_sizes[1] / 2;
    const int* row = ei;
    const int* col = ei + e;

    const int SMEM_UPD = (128 * APS + 64 * ARS + 192) * 4;   // 70,400 B
    const int SMEM_OUT = (64 * DH + 64 * 128) * 4;           // 49152

    cudaFuncSetAttribute(k_update, cudaFuncAttributeMaxDynamicSharedMemorySize, SMEM_UPD);
    cudaFuncSetAttribute(k_out,    cudaFuncAttributeMaxDynamicSharedMemorySize, SMEM_OUT);

    // build CSR (sorted by dst) once; reused by all 3 layers.
    // g_hist is zero here: static init on first run, k_out re-zeroes after.
    int nbn = (n + 255) / 256;
    k_hist<<<(e + 255) / 256, 256>>>(col, e);
    k_blocksum<<<nbn, 256>>>(n);
    k_offsets<<<nbn, 256>>>(n, e);
    k_scatter<<<(e + 255) / 256, 256>>>(row, col, e);

    k_prep_all<<<4, 256>>>(msg_w2, upd_w1, msg_b2, msg_w1, in_w, in_b);
    k_input<<<(n * DH + 255) / 256, 256>>>(x, in_w, in_b, n);

    int nb128 = (n + 127) / 128;
    for (int l = 0; l < 3; l++) {
        k_agg<<<(n + 15) / 16, 256>>>(msg_b1 + l * DH, n);
        const float* w1n = (l < 2) ? (msg_w1 + (l + 1) * 2 * DH * DH) : nullptr;
        k_update<<<nb128, 256, SMEM_UPD>>>(upd_w1 + l * 2 * DH * DH, upd_b1 + l * DH,
                                           upd_w2 + l * DH * DH, upd_b2 + l * DH,
                                           l, n, w1n);
    }
    k_out<<<(n + 63) / 64, 256, SMEM_OUT>>>(out_w, out_b, (float*)d_out, n);
}

// round 17
// speedup vs baseline: 1.0176x; 1.0019x over previous
#include <cuda_runtime.h>

#define NN 50000
#define EE 800000
#define DH 64
#define APS 68    // f32 A-tile row stride (conflict-free 32-bit frag loads)
#define ARS 136   // (hi,lo)-pair W-tile row stride

// ---- scratch (device globals; no allocation allowed) ----
__device__ float g_h[NN * DH];
__device__ float g_P[NN * DH];
__device__ float g_Q[NN * DH];
__device__ float g_aggH[NN * DH];
__device__ float g_W2U[3 * DH * DH];   // W2 @ U1b per layer
__device__ float g_b2U[3 * DH];        // b2 @ U1b per layer
__device__ float g_CWP[3 * DH];        // in_w @ W1a[0]
__device__ float g_CWQ[3 * DH];        // in_w @ W1b[0]
__device__ float g_cbP[DH];
__device__ float g_cbQ[DH];
__device__ int   g_hist[NN];
__device__ int   g_bsum[256];
__device__ int   g_off[NN + 1];
__device__ int   g_cur[NN];
__device__ int   g_rows[EE];

// ---- tf32 helpers ----
__device__ __forceinline__ void dec2(float a, float& hi, float& lo) {
    unsigned int hb;
    asm("cvt.rna.tf32.f32 %0, %1;" : "=r"(hb) : "f"(a));
    hi = __uint_as_float(hb);
    float r = a - hi;
    unsigned int lb;
    asm("cvt.rna.tf32.f32 %0, %1;" : "=r"(lb) : "f"(r));
    lo = __uint_as_float(lb);
}

#define MMA(c0, c1, c2, c3, a0, a1, a2, a3, b0, b1)                          \
    asm volatile("mma.sync.aligned.m16n8k8.row.col.f32.tf32.tf32.f32 "       \
                 "{%0,%1,%2,%3}, {%4,%5,%6,%7}, {%8,%9}, {%0,%1,%2,%3};"     \
                 : "+f"(c0), "+f"(c1), "+f"(c2), "+f"(c3)                    \
                 : "r"(a0), "r"(a1), "r"(a2), "r"(a3), "r"(b0), "r"(b1))

// stage 128x64 activation tile as PLAIN f32, row stride APS
#define STAGE_A(SRC)                                                         \
    _Pragma("unroll")                                                        \
    for (int it_ = 0; it_ < 8; it_++) {                                      \
        int q_ = it_ * 256 + t;                                              \
        int i_ = q_ >> 4, j4_ = (q_ & 15) * 4;                               \
        float4 v_ = make_float4(0.f, 0.f, 0.f, 0.f);                         \
        if (base + i_ < n) v_ = *(const float4*)&(SRC)[(base + i_) * DH + j4_]; \
        *(float4*)&As[i_ * APS + j4_] = v_;                                  \
    }

// prefetch a 64x64 weight tile into 16 registers (wq0..wq3), coalesced
#define LDW(SRC)                                                             \
    wq0 = *(const float4*)&(SRC)[((0 * 256 + t) >> 4) * 64 + ((0 * 256 + t) & 15) * 4]; \
    wq1 = *(const float4*)&(SRC)[((1 * 256 + t) >> 4) * 64 + ((1 * 256 + t) & 15) * 4]; \
    wq2 = *(const float4*)&(SRC)[((2 * 256 + t) >> 4) * 64 + ((2 * 256 + t) & 15) * 4]; \
    wq3 = *(const float4*)&(SRC)[((3 * 256 + t) >> 4) * 64 + ((3 * 256 + t) & 15) * 4];

// decompose the prefetched registers and store to WHL (no gmem latency)
#define STW                                                                  \
    {                                                                        \
        float4 wv_[4] = {wq0, wq1, wq2, wq3};                                \
        _Pragma("unroll")                                                    \
        for (int it_ = 0; it_ < 4; it_++) {                                  \
            int q_ = it_ * 256 + t;                                          \
            int k_ = q_ >> 4, j4_ = (q_ & 15) * 4;                           \
            float h0_, l0_, h1_, l1_;                                        \
            dec2(wv_[it_].x, h0_, l0_); dec2(wv_[it_].y, h1_, l1_);          \
            *(float4*)&WHL[k_ * ARS + 2 * j4_] = make_float4(h0_, l0_, h1_, l1_);     \
            dec2(wv_[it_].z, h0_, l0_); dec2(wv_[it_].w, h1_, l1_);          \
            *(float4*)&WHL[k_ * ARS + 2 * j4_ + 4] = make_float4(h0_, l0_, h1_, l1_); \
        }                                                                    \
    }

// one 128x64x64 GEMM pass via 3xTF32 mma; A decomposed on the fly.
#define MMA_PASS(ACC)                                                        \
    _Pragma("unroll 2")                                                      \
    for (int k0_ = 0; k0_ < 64; k0_ += 8) {                                  \
        float a00_ = As[(row0 + gq) * APS + k0_ + t4];                       \
        float a10_ = As[(row0 + gq + 8) * APS + k0_ + t4];                   \
        float a01_ = As[(row0 + gq) * APS + k0_ + t4 + 4];                   \
        float a11_ = As[(row0 + gq + 8) * APS + k0_ + t4 + 4];               \
        float h_, l_;                                                        \
        dec2(a00_, h_, l_);                                                  \
        unsigned ah0 = __float_as_uint(h_), al0 = __float_as_uint(l_);       \
        dec2(a10_, h_, l_);                                                  \
        unsigned ah1 = __float_as_uint(h_), al1 = __float_as_uint(l_);       \
        dec2(a01_, h_, l_);                                                  \
        unsigned ah2 = __float_as_uint(h_), al2 = __float_as_uint(l_);       \
        dec2(a11_, h_, l_);                                                  \
        unsigned ah3 = __float_as_uint(h_), al3 = __float_as_uint(l_);       \
        _Pragma("unroll")                                                    \
        for (int nt_ = 0; nt_ < 8; nt_++) {                                  \
            float2 fb0 = *(const float2*)&WHL[(k0_ + t4) * ARS + 2 * (nt_ * 8 + gq)];     \
            float2 fb1 = *(const float2*)&WHL[(k0_ + t4 + 4) * ARS + 2 * (nt_ * 8 + gq)]; \
            unsigned bh0 = __float_as_uint(fb0.x), bl0 = __float_as_uint(fb0.y); \
            unsigned bh1 = __float_as_uint(fb1.x), bl1 = __float_as_uint(fb1.y); \
            MMA(ACC[nt_][0], ACC[nt_][1], ACC[nt_][2], ACC[nt_][3],          \
                ah0, ah1, ah2, ah3, bh0, bh1);                               \
            MMA(ACC[nt_][0], ACC[nt_][1], ACC[nt_][2], ACC[nt_][3],          \
                ah0, ah1, ah2, ah3, bl0, bl1);                               \
            MMA(ACC[nt_][0], ACC[nt_][1], ACC[nt_][2], ACC[nt_][3],          \
                al0, al1, al2, al3, bh0, bh1);                               \
        }                                                                    \
    }

#define CLEAR_C(ACC)                                                         \
    _Pragma("unroll")                                                        \
    for (int nt_ = 0; nt_ < 8; nt_++)                                        \
        ACC[nt_][0] = ACC[nt_][1] = ACC[nt_][2] = ACC[nt_][3] = 0.f;

// classic f32 macro (k_out only)
#define GEMM_8x4(AS, I0, WS_PTR, WSTRIDE, ACC)                                  \
    _Pragma("unroll 4")                                                          \
    for (int k0 = 0; k0 < 64; k0 += 4) {                                         \
        float4 w0 = *(const float4*)&(WS_PTR)[(k0 + 0) * (WSTRIDE) + j0];        \
        float4 w1 = *(const float4*)&(WS_PTR)[(k0 + 1) * (WSTRIDE) + j0];        \
        float4 w2 = *(const float4*)&(WS_PTR)[(k0 + 2) * (WSTRIDE) + j0];        \
        float4 w3 = *(const float4*)&(WS_PTR)[(k0 + 3) * (WSTRIDE) + j0];        \
        _Pragma("unroll")                                                        \
        for (int r = 0; r < 8; r++) {                                            \
            float4 a4 = *(const float4*)&(AS)[((I0) + r) * DH + k0];             \
            ACC[r][0] = fmaf(a4.x, w0.x, ACC[r][0]);                             \
            ACC[r][1] = fmaf(a4.x, w0.y, ACC[r][1]);                             \
            ACC[r][2] = fmaf(a4.x, w0.z, ACC[r][2]);                             \
            ACC[r][3] = fmaf(a4.x, w0.w, ACC[r][3]);                             \
            ACC[r][0] = fmaf(a4.y, w1.x, ACC[r][0]);                             \
            ACC[r][1] = fmaf(a4.y, w1.y, ACC[r][1]);                             \
            ACC[r][2] = fmaf(a4.y, w1.z, ACC[r][2]);                             \
            ACC[r][3] = fmaf(a4.y, w1.w, ACC[r][3]);                             \
            ACC[r][0] = fmaf(a4.z, w2.x, ACC[r][0]);                             \
            ACC[r][1] = fmaf(a4.z, w2.y, ACC[r][1]);                             \
            ACC[r][2] = fmaf(a4.z, w2.z, ACC[r][2]);                             \
            ACC[r][3] = fmaf(a4.z, w2.w, ACC[r][3]);                             \
            ACC[r][0] = fmaf(a4.w, w3.x, ACC[r][0]);                             \
            ACC[r][1] = fmaf(a4.w, w3.y, ACC[r][1]);                             \
            ACC[r][2] = fmaf(a4.w, w3.z, ACC[r][2]);                             \
            ACC[r][3] = fmaf(a4.w, w3.w, ACC[r][3]);                             \
        }                                                                        \
    }

// =====================================================================
// Fused input: h = x@in_w + in_b ; P0 = x@CWP + cbP ; Q0 = x@CWQ + cbQ
// =====================================================================
__global__ void k_input(const float* __restrict__ x, const float* __restrict__ w,
                        const float* __restrict__ b, int n) {
    int t = blockIdx.x * blockDim.x + threadIdx.x;
    if (t >= n * DH) return;
    int i = t / DH, j = t % DH;
    float x0 = x[i * 3 + 0], x1 = x[i * 3 + 1], x2 = x[i * 3 + 2];
    g_h[t] = fmaf(x0, w[0 * DH + j], fmaf(x1, w[1 * DH + j],
             fmaf(x2, w[2 * DH + j], b[j])));
    g_P[t] = fmaf(x0, g_CWP[0 * DH + j], fmaf(x1, g_CWP[1 * DH + j],
             fmaf(x2, g_CWP[2 * DH + j], g_cbP[j])));
    g_Q[t] = fmaf(x0, g_CWQ[0 * DH + j], fmaf(x1, g_CWQ[1 * DH + j],
             fmaf(x2, g_CWQ[2 * DH + j], g_cbQ[j])));
}

// =====================================================================
// Counting sort of edges by destination (built once, used 3 layers)
// =====================================================================
__global__ void k_zero_hist(int n) {
    int t = blockIdx.x * blockDim.x + threadIdx.x;
    if (t < n) g_hist[t] = 0;
}
__global__ void k_hist(const int* __restrict__ col, int e) {
    int t = blockIdx.x * blockDim.x + threadIdx.x;
    if (t < e) atomicAdd(&g_hist[col[t]], 1);
}
__global__ void k_blocksum(int n) {
    __shared__ int ss[256];
    int t = threadIdx.x, i = blockIdx.x * 256 + t;
    ss[t] = (i < n) ? g_hist[i] : 0;
    __syncthreads();
    for (int o = 128; o > 0; o >>= 1) {
        if (t < o) ss[t] += ss[t + o];
        __syncthreads();
    }
    if (t == 0) g_bsum[blockIdx.x] = ss[0];
}
__global__ void k_offsets(int n, int e) {
    __shared__ int ss[256];
    int t = threadIdx.x, i = blockIdx.x * 256 + t;
    ss[t] = (t < blockIdx.x) ? g_bsum[t] : 0;
    __syncthreads();
    for (int o = 128; o > 0; o >>= 1) {
        if (t < o) ss[t] += ss[t + o];
        __syncthreads();
    }
    int bpre = ss[0];
    __syncthreads();
    int h = (i < n) ? g_hist[i] : 0;
    ss[t] = h;
    __syncthreads();
    for (int o = 1; o < 256; o <<= 1) {
        int v = (t >= o) ? ss[t - o] : 0;
        __syncthreads();
        ss[t] += v;
        __syncthreads();
    }
    int excl = ss[t] - h + bpre;
    if (i < n) {
        g_off[i] = excl; g_cur[i] = excl;
        if (i == n - 1) g_off[n] = e;
    }
}
__global__ void k_scatter(const int* __restrict__ row, const int* __restrict__ col,
                          int e) {
    int t = blockIdx.x * blockDim.x + threadIdx.x;
    if (t >= e) return;
    int c = col[t];
    int pos = atomicAdd(&g_cur[c], 1);
    g_rows[pos] = row[t];
}

// =====================================================================
// Precompute: blocks 0..2 -> W2U[l], b2U[l]; block 3 -> input composites
// =====================================================================
__global__ void k_prep_all(const float* __restrict__ msg_w2,
                           const float* __restrict__ upd_w1,
                           const float* __restrict__ msg_b2,
                           const float* __restrict__ msg_w1,
                           const float* __restrict__ in_w,
                           const float* __restrict__ in_b) {
    int t = threadIdx.x;
    if (blockIdx.x < 3) {
        int l = blockIdx.x;
        const float* w2  = msg_w2 + l * DH * DH;
        const float* u1b = upd_w1 + l * 2 * DH * DH + DH * DH;
        const float* b2  = msg_b2 + l * DH;
        __shared__ __align__(16) float W2s[DH * DH];
        __shared__ __align__(16) float U1s[DH * DH];
        __shared__ float b2s[DH];
        for (int q = t; q < DH * DH / 4; q += 256) {
            *(float4*)&W2s[q * 4] = *(const float4*)&w2[q * 4];
            *(float4*)&U1s[q * 4] = *(const float4*)&u1b[q * 4];
        }
        if (t < DH) b2s[t] = b2[t];
        __syncthreads();
        for (int idx = t; idx < DH * DH; idx += 256) {
            int k = idx >> 6, j = idx & 63;
            float s = 0.f;
            #pragma unroll 8
            for (int m = 0; m < DH; m++) s = fmaf(W2s[k * DH + m], U1s[m * DH + j], s);
            g_W2U[l * DH * DH + idx] = s;
        }
        if (t < DH) {
            float s = 0.f;
            #pragma unroll 8
            for (int m = 0; m < DH; m++) s = fmaf(b2s[m], U1s[m * DH + t], s);
            g_b2U[l * DH + t] = s;
        }
    } else {
        __shared__ __align__(16) float W1s[2 * DH * DH];
        __shared__ float iws[3 * DH];
        __shared__ float ibs[DH];
        for (int q = t; q < 2 * DH * DH / 4; q += 256)
            *(float4*)&W1s[q * 4] = *(const float4*)&msg_w1[q * 4];
        if (t < 3 * DH) iws[t] = in_w[t];
        if (t < DH) ibs[t] = in_b[t];
        __syncthreads();
        for (int idx = t; idx < 3 * DH; idx += 256) {
            int r = idx >> 6, j = idx & 63;
            float sp = 0.f, sq = 0.f;
            #pragma unroll 8
            for (int k = 0; k < DH; k++) {
                float iv = iws[r * DH + k];
                sp = fmaf(iv, W1s[k * DH + j], sp);
                sq = fmaf(iv, W1s[(DH + k) * DH + j], sq);
            }
            g_CWP[idx] = sp; g_CWQ[idx] = sq;
        }
        if (t < DH) {
            float sp = 0.f, sq = 0.f;
            #pragma unroll 8
            for (int k = 0; k < DH; k++) {
                sp = fmaf(ibs[k], W1s[k * DH + t], sp);
                sq = fmaf(ibs[k], W1s[(DH + k) * DH + t], sq);
            }
            g_cbP[t] = sp; g_cbQ[t] = sq;
        }
    }
}

// =====================================================================
// CSR aggregation: aggH[v] = sum_{e: dst=v} relu(P[src_e] + Q[v] + b1)
// =====================================================================
__global__ void __launch_bounds__(256)
k_agg(const float* __restrict__ b1, int n) {
    int node = blockIdx.x * 16 + (threadIdx.x >> 4);
    int l4 = (threadIdx.x & 15) * 4;
    if (node >= n) return;
    int s = g_off[node], en = g_off[node + 1];
    float4 q = *(const float4*)&g_Q[node * DH + l4];
    float4 b = *(const float4*)&b1[l4];
    q.x += b.x; q.y += b.y; q.z += b.z; q.w += b.w;
    float4 acc = make_float4(0.f, 0.f, 0.f, 0.f);
    int e = s;
    for (; e + 4 <= en; e += 4) {
        int r0 = __ldg(&g_rows[e + 0]);
        int r1 = __ldg(&g_rows[e + 1]);
        int r2 = __ldg(&g_rows[e + 2]);
        int r3 = __ldg(&g_rows[e + 3]);
        float4 p0 = *(const float4*)&g_P[r0 * DH + l4];
        float4 p1 = *(const float4*)&g_P[r1 * DH + l4];
        float4 p2 = *(const float4*)&g_P[r2 * DH + l4];
        float4 p3 = *(const float4*)&g_P[r3 * DH + l4];
        acc.x += fmaxf(p0.x + q.x, 0.f) + fmaxf(p1.x + q.x, 0.f)
               + fmaxf(p2.x + q.x, 0.f) + fmaxf(p3.x + q.x, 0.f);
        acc.y += fmaxf(p0.y + q.y, 0.f) + fmaxf(p1.y + q.y, 0.f)
               + fmaxf(p2.y + q.y, 0.f) + fmaxf(p3.y + q.y, 0.f);
        acc.z += fmaxf(p0.z + q.z, 0.f) + fmaxf(p1.z + q.z, 0.f)
               + fmaxf(p2.z + q.z, 0.f) + fmaxf(p3.z + q.z, 0.f);
        acc.w += fmaxf(p0.w + q.w, 0.f) + fmaxf(p1.w + q.w, 0.f)
               + fmaxf(p2.w + q.w, 0.f) + fmaxf(p3.w + q.w, 0.f);
    }
    for (; e < en; e++) {
        int rr = __ldg(&g_rows[e]);
        float4 p = *(const float4*)&g_P[rr * DH + l4];
        acc.x += fmaxf(p.x + q.x, 0.f);
        acc.y += fmaxf(p.y + q.y, 0.f);
        acc.z += fmaxf(p.z + q.z, 0.f);
        acc.w += fmaxf(p.w + q.w, 0.f);
    }
    *(float4*)&g_aggH[node * DH + l4] = acc;
}

// =====================================================================
// Node update via 3xTF32 mma, software-pipelined W staging:
// the next pass's W tile is prefetched into registers BEFORE the current
// MMA pass, so its gmem latency overlaps tensor work. occ 3.
// =====================================================================
__global__ void __launch_bounds__(256, 3)
k_update(const float* __restrict__ u1a, const float* __restrict__ ub1,
         const float* __restrict__ u2, const float* __restrict__ ub2,
         int l, int n, const float* __restrict__ w1_next) {
    extern __shared__ float sm[];
    float* As   = sm;                 // [128][APS] plain f32
    float* WHL  = sm + 128 * APS;     // [64][ARS]  k-major (hi,lo) pairs
    float* ub1s = WHL + 64 * ARS;
    float* ub2s = ub1s + 64;
    float* b2Us = ub2s + 64;
    int t = threadIdx.x;
    int w = t >> 5, lane = t & 31;
    int gq = lane >> 2, t4 = lane & 3;
    int base = blockIdx.x * 128;
    int row0 = w * 16;
    float4 wq0, wq1, wq2, wq3;        // W prefetch registers

    if (t < 64) { ub1s[t] = ub1[t]; ub2s[t] = ub2[t]; b2Us[t] = g_b2U[l * DH + t]; }

    float C[8][4];
    CLEAR_C(C)

    const float* w2u = g_W2U + l * DH * DH;

    // ---- pass 0: h @ U1a  (W(u1a) prefetched immediately) ----
    LDW(u1a)
    STAGE_A(g_h)
    STW
    __syncthreads();
    LDW(w2u)                 // prefetch pass-1 W during pass-0 MMA
    MMA_PASS(C)
    __syncthreads();

    // ---- pass 1: aggH @ W2U ----
    STAGE_A(g_aggH)
    STW
    __syncthreads();
    LDW(u2)                  // prefetch U2 during pass-1 MMA
    MMA_PASS(C)
    __syncthreads();

    // epilogue 1: hid = relu(pre + deg*b2U + ub1) -> As (f32); store U2
    {
        int i0g = base + row0 + gq, i1g = i0g + 8;
        float dg0 = (i0g < n) ? (float)(g_off[i0g + 1] - g_off[i0g]) : 0.f;
        float dg1 = (i1g < n) ? (float)(g_off[i1g + 1] - g_off[i1g]) : 0.f;
        #pragma unroll
        for (int nt = 0; nt < 8; nt++) {
            int j0c = nt * 8 + 2 * t4, j1c = j0c + 1;
            float v00 = fmaxf(C[nt][0] + dg0 * b2Us[j0c] + ub1s[j0c], 0.f);
            float v01 = fmaxf(C[nt][1] + dg0 * b2Us[j1c] + ub1s[j1c], 0.f);
            float v10 = fmaxf(C[nt][2] + dg1 * b2Us[j0c] + ub1s[j0c], 0.f);
            float v11 = fmaxf(C[nt][3] + dg1 * b2Us[j1c] + ub1s[j1c], 0.f);
            *(float2*)&As[(row0 + gq) * APS + j0c] = make_float2(v00, v01);
            *(float2*)&As[(row0 + gq + 8) * APS + j0c] = make_float2(v10, v11);
        }
    }
    STW
    __syncthreads();

    CLEAR_C(C)
    if (w1_next) { LDW(w1_next) }   // prefetch W1a' during U2 MMA
    MMA_PASS(C)
    __syncthreads();

    // epilogue 2: h = relu(C + ub2) -> gmem (+ As if P/Q needed)
    {
        int i0g = base + row0 + gq, i1g = i0g + 8;
        #pragma unroll
        for (int nt = 0; nt < 8; nt++) {
            int j0c = nt * 8 + 2 * t4, j1c = j0c + 1;
            float v00 = fmaxf(C[nt][0] + ub2s[j0c], 0.f);
            float v01 = fmaxf(C[nt][1] + ub2s[j1c], 0.f);
            float v10 = fmaxf(C[nt][2] + ub2s[j0c], 0.f);
            float v11 = fmaxf(C[nt][3] + ub2s[j1c], 0.f);
            if (i0g < n) *(float2*)&g_h[i0g * DH + j0c] = make_float2(v00, v01);
            if (i1g < n) *(float2*)&g_h[i1g * DH + j0c] = make_float2(v10, v11);
            if (w1_next) {
                *(float2*)&As[(row0 + gq) * APS + j0c] = make_float2(v00, v01);
                *(float2*)&As[(row0 + gq + 8) * APS + j0c] = make_float2(v10, v11);
            }
        }
    }

    if (w1_next) {
        // ---- P pass ----
        STW
        __syncthreads();
        CLEAR_C(C)
        LDW(w1_next + 64 * DH)       // prefetch W1b' during P MMA
        MMA_PASS(C)
        {
            int i0g = base + row0 + gq, i1g = i0g + 8;
            #pragma unroll
            for (int nt = 0; nt < 8; nt++) {
                int j0c = nt * 8 + 2 * t4;
                if (i0g < n) *(float2*)&g_P[i0g * DH + j0c] = make_float2(C[nt][0], C[nt][1]);
                if (i1g < n) *(float2*)&g_P[i1g * DH + j0c] = make_float2(C[nt][2], C[nt][3]);
            }
        }
        __syncthreads();
        // ---- Q pass ----
        STW
        __syncthreads();
        CLEAR_C(C)
        MMA_PASS(C)
        {
            int i0g = base + row0 + gq, i1g = i0g + 8;
            #pragma unroll
            for (int nt = 0; nt < 8; nt++) {
                int j0c = nt * 8 + 2 * t4;
                if (i0g < n) *(float2*)&g_Q[i0g * DH + j0c] = make_float2(C[nt][0], C[nt][1]);
                if (i1g < n) *(float2*)&g_Q[i1g * DH + j0c] = make_float2(C[nt][2], C[nt][3]);
            }
        }
    }
}

// =====================================================================
// Output: out = h @ out_w + out_b   ([N,64] @ [64,128])
// =====================================================================
__global__ void __launch_bounds__(256, 4)
k_out(const float* __restrict__ ow, const float* __restrict__ ob,
      float* __restrict__ out, int n) {
    extern __shared__ float sm[];
    float* As = sm;            // [64][64]
    float* Ws = sm + 64 * DH;  // [64][128]
    int t = threadIdx.x;
    int base = blockIdx.x * 64;

    #pragma unroll
    for (int it = 0; it < 4; it++) {
        int q = it * 256 + t;
        int i = q >> 4, j4 = (q & 15) * 4;
        float4 v = make_float4(0.f, 0.f, 0.f, 0.f);
        if (base + i < n) v = *(const float4*)&g_h[(base + i) * DH + j4];
        *(float4*)&As[i * DH + j4] = v;
    }
    #pragma unroll
    for (int it = 0; it < 8; it++) {
        int q = it * 256 + t;
        int k = q >> 5, j4 = (q & 31) * 4;
        *(float4*)&Ws[k * 128 + j4] = *(const float4*)&ow[k * 128 + j4];
    }
    __syncthreads();

    int tx = t & 31, ty = t >> 5;
    int j0 = tx * 4, i0 = ty * 8;
    float acc[8][4];
    #pragma unroll
    for (int r = 0; r < 8; r++) {
        acc[r][0] = ob[j0 + 0]; acc[r][1] = ob[j0 + 1];
        acc[r][2] = ob[j0 + 2]; acc[r][3] = ob[j0 + 3];
    }

    GEMM_8x4(As, i0, Ws, 128, acc)

    #pragma unroll
    for (int r = 0; r < 8; r++) {
        int i = base + i0 + r;
        if (i < n)
            *(float4*)&out[i * 128 + j0] =
                make_float4(acc[r][0], acc[r][1], acc[r][2], acc[r][3]);
    }
}

// =====================================================================
// Launcher
// =====================================================================
extern "C" void kernel_launch(void* const* d_in, const int* in_sizes, int n_in,
                              void* d_out, int out_size) {
    const float* x      = (const float*)d_in[0];
    const int*   ei     = (const int*)  d_in[1];
    const float* in_w   = (const float*)d_in[2];
    const float* in_b   = (const float*)d_in[3];
    const float* msg_w1 = (const float*)d_in[4];
    const float* msg_b1 = (const float*)d_in[5];
    const float* msg_w2 = (const float*)d_in[6];
    const float* msg_b2 = (const float*)d_in[7];
    const float* upd_w1 = (const float*)d_in[8];
    const float* upd_b1 = (const float*)d_in[9];
    const float* upd_w2 = (const float*)d_in[10];
    const float* upd_b2 = (const float*)d_in[11];
    const float* out_w  = (const float*)d_in[12];
    const float* out_b  = (const float*)d_in[13];

    int n = in_sizes[0] / 3;
    int e = in_sizes[1] / 2;
    const int* row = ei;
    const int* col = ei + e;

    const int SMEM_UPD = (128 * APS + 64 * ARS + 192) * 4;   // 70,400 B
    const int SMEM_OUT = (64 * DH + 64 * 128) * 4;           // 49152

    cudaFuncSetAttribute(k_update, cudaFuncAttributeMaxDynamicSharedMemorySize, SMEM_UPD);
    cudaFuncSetAttribute(k_out,    cudaFuncAttributeMaxDynamicSharedMemorySize, SMEM_OUT);

    // build CSR (sorted by dst) once; reused by all 3 layers
    int nbn = (n + 255) / 256;
    k_zero_hist<<<nbn, 256>>>(n);
    k_hist<<<(e + 255) / 256, 256>>>(col, e);
    k_blocksum<<<nbn, 256>>>(n);
    k_offsets<<<nbn, 256>>>(n, e);
    k_scatter<<<(e + 255) / 256, 256>>>(row, col, e);

    k_prep_all<<<4, 256>>>(msg_w2, upd_w1, msg_b2, msg_w1, in_w, in_b);
    k_input<<<(n * DH + 255) / 256, 256>>>(x, in_w, in_b, n);

    int nb128 = (n + 127) / 128;
    for (int l = 0; l < 3; l++) {
        k_agg<<<(n + 15) / 16, 256>>>(msg_b1 + l * DH, n);
        const float* w1n = (l < 2) ? (msg_w1 + (l + 1) * 2 * DH * DH) : nullptr;
        k_update<<<nb128, 256, SMEM_UPD>>>(upd_w1 + l * 2 * DH * DH, upd_b1 + l * DH,
                                           upd_w2 + l * DH * DH, upd_b2 + l * DH,
                                           l, n, w1n);
    }
    k_out<<<(n + 63) / 64, 256, SMEM_OUT>>>(out_w, out_b, (float*)d_out, n);
}